// round 2
// baseline (speedup 1.0000x reference)
#include <cuda_runtime.h>
#include <cstdint>
#include <cstddef>

#define S_LEN   64
#define N_SEQ   65536
#define IN_DIM  2
#define EMB     64
#define RDIM    128
#define G4      512     // 4*R
#define KDIM    192     // EMB + R
#define OUT_DIM 5

#define TILE     64     // sequences per CTA
#define NTHREADS 512
#define KC       16     // k-chunk size
#define NCHUNK   (KDIM / KC)   // 12

// -------- device scratch (no allocations allowed) --------
__device__ __align__(16) float g_Wt[KDIM * G4];   // [k][j], k-major transposed weights
__device__ __align__(16) float g_bias[G4];        // b_ih + b_hh

// -------- small helpers --------
__device__ __forceinline__ unsigned long long dup2(float x) {
    unsigned long long r;
    asm("mov.b64 %0, {%1, %1};" : "=l"(r) : "f"(x));
    return r;
}
__device__ __forceinline__ void fma2(unsigned long long& d, unsigned long long a, unsigned long long b) {
    asm("fma.rn.f32x2 %0, %1, %2, %0;" : "+l"(d) : "l"(a), "l"(b));
}
__device__ __forceinline__ float2 unpk(unsigned long long v) {
    float2 f;
    asm("mov.b64 {%0, %1}, %2;" : "=f"(f.x), "=f"(f.y) : "l"(v));
    return f;
}
__device__ __forceinline__ void cp_async16(uint32_t smem_dst, const void* gsrc) {
    asm volatile("cp.async.cg.shared.global [%0], [%1], 16;" :: "r"(smem_dst), "l"(gsrc));
}
__device__ __forceinline__ void cp_commit() { asm volatile("cp.async.commit_group;"); }
template <int NW>
__device__ __forceinline__ void cp_wait() { asm volatile("cp.async.wait_group %0;" :: "n"(NW)); }

__device__ __forceinline__ float sigf(float x) {
    return __fdividef(1.f, 1.f + __expf(-x));
}
__device__ __forceinline__ float tanh_(float x) {
    // tanh(x) = 2*sigmoid(2x) - 1  (MUFU.EX2 + MUFU.RCP based, ~1e-7 rel err)
    return fmaf(2.f, sigf(2.f * x), -1.f);
}

// -------- prep: transpose weights to k-major, fuse biases --------
__global__ void prep_kernel(const float* __restrict__ W_ih, const float* __restrict__ W_hh,
                            const float* __restrict__ b_ih, const float* __restrict__ b_hh) {
    int k = blockIdx.x;
    for (int j = threadIdx.x; j < G4; j += blockDim.x) {
        float w = (k < EMB) ? W_ih[j * EMB + k] : W_hh[j * RDIM + (k - EMB)];
        g_Wt[k * G4 + j] = w;
        if (k == 0) g_bias[j] = b_ih[j] + b_hh[j];
    }
}

// -------- main persistent LSTM kernel --------
// SMEM layout (floats):
//  sAct [192][64]  : rows 0..63 = embeddings (rewritten/step), rows 64..191 = h (persistent)
//  sC   [128][64]  : cell state (persistent)
//  sW   [2][16*512]: double-buffered weight chunks
//  sX   [128]      : x staging (64 seq * 2)
//  sRed [64*8*5]   : output-head partial sums
//  sM   [64] (int) : mask staging
__global__ void __launch_bounds__(NTHREADS, 1)
lstm_kernel(const float* __restrict__ input_data,
            const float* __restrict__ h0,
            const float* __restrict__ c0,
            const int*   __restrict__ ped_mask,
            const float* __restrict__ W_emb,
            const float* __restrict__ b_emb,
            const float* __restrict__ W_out,
            const float* __restrict__ b_out,
            float* __restrict__ out_y,
            float* __restrict__ out_h,
            float* __restrict__ out_c)
{
    extern __shared__ float sm[];
    float* sAct = sm;                   // 12288 floats
    float* sC   = sm + 12288;           // 8192
    float* sW   = sm + 20480;           // 16384
    float* sX   = sm + 36864;           // 128
    float* sRed = sm + 36992;           // 2560
    int*   sM   = (int*)(sm + 39552);   // 64 ints

    const int t  = threadIdx.x;
    const int n0 = blockIdx.x * TILE;

    const int sb = t & 15;       // seq-block (4 seqs each)
    const int rb = t >> 4;       // 0..31 -> r0 = rb*4
    const uint32_t sWbase = (uint32_t)__cvta_generic_to_shared(sW);

    // ---- init h, c into SMEM ----
    {
        int s  = t >> 3;
        int r0 = (t & 7) << 4;
        #pragma unroll
        for (int i = 0; i < 16; i += 4) {
            float4 hv = *(const float4*)&h0[(size_t)(n0 + s) * RDIM + r0 + i];
            float4 cv = *(const float4*)&c0[(size_t)(n0 + s) * RDIM + r0 + i];
            sAct[(EMB + r0 + i + 0) * TILE + s] = hv.x;
            sAct[(EMB + r0 + i + 1) * TILE + s] = hv.y;
            sAct[(EMB + r0 + i + 2) * TILE + s] = hv.z;
            sAct[(EMB + r0 + i + 3) * TILE + s] = hv.w;
            sC[(r0 + i + 0) * TILE + s] = cv.x;
            sC[(r0 + i + 1) * TILE + s] = cv.y;
            sC[(r0 + i + 2) * TILE + s] = cv.z;
            sC[(r0 + i + 3) * TILE + s] = cv.w;
        }
    }

    #pragma unroll 1
    for (int st = 0; st < S_LEN; ++st) {
        __syncthreads();   // prev-step consumers done; safe to restage
        if (t < 128) {
            sX[t] = input_data[((size_t)st * N_SEQ + n0) * IN_DIM + t];
        } else if (t < 192) {
            sM[t - 128] = ped_mask[(size_t)st * N_SEQ + n0 + (t - 128)];
        }
        __syncthreads();

        // ---- prefetch weight chunk 0 (overlaps embedding) ----
        {
            const float4* src = (const float4*)(g_Wt);
            #pragma unroll
            for (int i = 0; i < 4; ++i) {
                int f = t + i * 512;
                cp_async16(sWbase + (uint32_t)f * 16u, src + f);
            }
            cp_commit();
        }

        // ---- embedding: e = relu(x @ W_emb^T + b_emb) -> sAct rows [0,64) ----
        {
            int s  = t & 63;
            int kb = (t >> 6) * 8;
            float x0 = sX[2 * s], x1 = sX[2 * s + 1];
            #pragma unroll
            for (int i = 0; i < 8; ++i) {
                int k = kb + i;
                float e = fmaf(W_emb[k * 2], x0, fmaf(W_emb[k * 2 + 1], x1, b_emb[k]));
                sAct[k * TILE + s] = fmaxf(e, 0.f);
            }
        }

        // ---- accumulators = fused bias (packed f32x2: gate pairs) ----
        unsigned long long acc[4][8];
        #pragma unroll
        for (int ty = 0; ty < 4; ++ty) {
            const unsigned long long* bp =
                (const unsigned long long*)&g_bias[ty * 128 + rb * 4];
            unsigned long long b0 = bp[0], b1 = bp[1];
            #pragma unroll
            for (int ss = 0; ss < 4; ++ss) { acc[ss][ty * 2] = b0; acc[ss][ty * 2 + 1] = b1; }
        }
        __syncthreads();   // embeddings visible

        // ---- gates GEMM: 12 chunks of K=16, cp.async double-buffered ----
        #pragma unroll 1
        for (int c = 0; c < NCHUNK; ++c) {
            cp_wait<0>();
            __syncthreads();      // everyone sees chunk c; prev reads of other buf done
            if (c + 1 < NCHUNK) {
                const float4* src = (const float4*)(g_Wt + (c + 1) * KC * G4);
                uint32_t dbase = sWbase + (uint32_t)(((c + 1) & 1) * (KC * G4)) * 4u;
                #pragma unroll
                for (int i = 0; i < 4; ++i) {
                    int f = t + i * 512;
                    cp_async16(dbase + (uint32_t)f * 16u, src + f);
                }
                cp_commit();
            }
            const float* wbuf = sW + (c & 1) * (KC * G4);
            #pragma unroll
            for (int kk = 0; kk < KC; ++kk) {
                int k = c * KC + kk;
                float4 a4 = *(const float4*)&sAct[k * TILE + sb * 4];
                unsigned long long da0 = dup2(a4.x), da1 = dup2(a4.y);
                unsigned long long da2 = dup2(a4.z), da3 = dup2(a4.w);
                #pragma unroll
                for (int ty = 0; ty < 4; ++ty) {
                    const unsigned long long* wp =
                        (const unsigned long long*)&wbuf[kk * G4 + ty * 128 + rb * 4];
                    unsigned long long w0 = wp[0], w1 = wp[1];
                    fma2(acc[0][ty * 2], da0, w0); fma2(acc[0][ty * 2 + 1], da0, w1);
                    fma2(acc[1][ty * 2], da1, w0); fma2(acc[1][ty * 2 + 1], da1, w1);
                    fma2(acc[2][ty * 2], da2, w0); fma2(acc[2][ty * 2 + 1], da2, w1);
                    fma2(acc[3][ty * 2], da3, w0); fma2(acc[3][ty * 2 + 1], da3, w1);
                }
            }
        }
        __syncthreads();   // all GEMM reads of sAct/h done before overwrite

        // ---- elementwise LSTM cell (gates live in regs) ----
        #pragma unroll
        for (int ss = 0; ss < 4; ++ss) {
            int s = sb * 4 + ss;
            int m = sM[s];
            float ga[4][4];
            #pragma unroll
            for (int ty = 0; ty < 4; ++ty) {
                float2 v0 = unpk(acc[ss][ty * 2]);
                float2 v1 = unpk(acc[ss][ty * 2 + 1]);
                ga[ty][0] = v0.x; ga[ty][1] = v0.y; ga[ty][2] = v1.x; ga[ty][3] = v1.y;
            }
            #pragma unroll
            for (int rr = 0; rr < 4; ++rr) {
                int r = rb * 4 + rr;
                float iv = sigf(ga[0][rr]);
                float fv = sigf(ga[1][rr]);
                float gv = tanh_(ga[2][rr]);
                float ov = sigf(ga[3][rr]);
                float cold = sC[r * TILE + s];
                float cnew = fmaf(fv, cold, iv * gv);
                float hnew = ov * tanh_(cnew);
                if (m) {
                    sC[r * TILE + s] = cnew;
                    sAct[(EMB + r) * TILE + s] = hnew;   // h_new == stored h when masked
                }
            }
        }
        __syncthreads();

        // ---- output head: out = mask ? h @ W_out^T + b_out : 0 ----
        {
            int s = t & 63;
            int part = t >> 6;  // 8 parts x 16 r
            float o0 = 0, o1 = 0, o2 = 0, o3 = 0, o4 = 0;
            #pragma unroll
            for (int rr = 0; rr < 16; ++rr) {
                int r = part * 16 + rr;
                float h = sAct[(EMB + r) * TILE + s];
                o0 = fmaf(h, W_out[0 * RDIM + r], o0);
                o1 = fmaf(h, W_out[1 * RDIM + r], o1);
                o2 = fmaf(h, W_out[2 * RDIM + r], o2);
                o3 = fmaf(h, W_out[3 * RDIM + r], o3);
                o4 = fmaf(h, W_out[4 * RDIM + r], o4);
            }
            float* rp = &sRed[(s * 8 + part) * 5];
            rp[0] = o0; rp[1] = o1; rp[2] = o2; rp[3] = o3; rp[4] = o4;
        }
        __syncthreads();
        if (t < 320) {
            int s = t / 5, o = t % 5;
            float a = 0.f;
            if (sM[s]) {
                #pragma unroll
                for (int p = 0; p < 8; ++p) a += sRed[(s * 8 + p) * 5 + o];
                a += b_out[o];
            }
            out_y[((size_t)st * N_SEQ + (n0 + s)) * OUT_DIM + o] = a;
        }
    }

    __syncthreads();
    // ---- final h, c writeback ----
    {
        int s  = t >> 3;
        int r0 = (t & 7) << 4;
        #pragma unroll
        for (int i = 0; i < 16; i += 4) {
            float4 hv, cv;
            hv.x = sAct[(EMB + r0 + i + 0) * TILE + s];
            hv.y = sAct[(EMB + r0 + i + 1) * TILE + s];
            hv.z = sAct[(EMB + r0 + i + 2) * TILE + s];
            hv.w = sAct[(EMB + r0 + i + 3) * TILE + s];
            cv.x = sC[(r0 + i + 0) * TILE + s];
            cv.y = sC[(r0 + i + 1) * TILE + s];
            cv.z = sC[(r0 + i + 2) * TILE + s];
            cv.w = sC[(r0 + i + 3) * TILE + s];
            *(float4*)&out_h[(size_t)(n0 + s) * RDIM + r0 + i] = hv;
            *(float4*)&out_c[(size_t)(n0 + s) * RDIM + r0 + i] = cv;
        }
    }
}

extern "C" void kernel_launch(void* const* d_in, const int* in_sizes, int n_in,
                              void* d_out, int out_size) {
    const float* input_data = (const float*)d_in[0];
    const float* h0         = (const float*)d_in[1];
    const float* c0         = (const float*)d_in[2];
    const int*   ped        = (const int*)  d_in[3];
    const float* W_emb      = (const float*)d_in[4];
    const float* b_emb      = (const float*)d_in[5];
    const float* W_ih       = (const float*)d_in[6];
    const float* W_hh       = (const float*)d_in[7];
    const float* b_ih       = (const float*)d_in[8];
    const float* b_hh       = (const float*)d_in[9];
    const float* W_out      = (const float*)d_in[10];
    const float* b_out      = (const float*)d_in[11];

    float* out   = (float*)d_out;
    float* out_y = out;                                      // [S][N][5]
    float* out_h = out + (size_t)S_LEN * N_SEQ * OUT_DIM;    // [N][128]
    float* out_c = out_h + (size_t)N_SEQ * RDIM;             // [N][128]

    prep_kernel<<<KDIM, 256>>>(W_ih, W_hh, b_ih, b_hh);

    const size_t SMEM = 158464;  // bytes
    cudaFuncSetAttribute(lstm_kernel, cudaFuncAttributeMaxDynamicSharedMemorySize, (int)SMEM);
    lstm_kernel<<<N_SEQ / TILE, NTHREADS, SMEM>>>(
        input_data, h0, c0, ped, W_emb, b_emb, W_out, b_out, out_y, out_h, out_c);
}

// round 3
// speedup vs baseline: 1.0003x; 1.0003x over previous
#include <cuda_runtime.h>
#include <cstdint>
#include <cstddef>

#define S_LEN   64
#define N_SEQ   65536
#define IN_DIM  2
#define EMB     64
#define RDIM    128
#define G4      512     // 4*R
#define KDIM    192     // EMB + R
#define OUT_DIM 5

#define TILE     64     // sequences per CTA
#define NTHREADS 512
#define KC       16     // k-chunk size
#define NCHUNK   (KDIM / KC)   // 12

// -------- device scratch (no allocations allowed) --------
__device__ __align__(16) float g_Wt[KDIM * G4];   // [k][j], k-major transposed weights
__device__ __align__(16) float g_bias[G4];        // b_ih + b_hh

// -------- small helpers --------
__device__ __forceinline__ unsigned long long dup2(float x) {
    unsigned long long r;
    asm("mov.b64 %0, {%1, %1};" : "=l"(r) : "f"(x));
    return r;
}
__device__ __forceinline__ void fma2(unsigned long long& d, unsigned long long a, unsigned long long b) {
    asm("fma.rn.f32x2 %0, %1, %2, %0;" : "+l"(d) : "l"(a), "l"(b));
}
__device__ __forceinline__ float2 unpk(unsigned long long v) {
    float2 f;
    asm("mov.b64 {%0, %1}, %2;" : "=f"(f.x), "=f"(f.y) : "l"(v));
    return f;
}
__device__ __forceinline__ void cp_async16(uint32_t smem_dst, const void* gsrc) {
    asm volatile("cp.async.cg.shared.global [%0], [%1], 16;" :: "r"(smem_dst), "l"(gsrc));
}
__device__ __forceinline__ void cp_commit() { asm volatile("cp.async.commit_group;"); }
template <int NW>
__device__ __forceinline__ void cp_wait() { asm volatile("cp.async.wait_group %0;" :: "n"(NW)); }

__device__ __forceinline__ float sigf(float x) {
    return __fdividef(1.f, 1.f + __expf(-x));
}
__device__ __forceinline__ float tanh_(float x) {
    // tanh(x) = 2*sigmoid(2x) - 1  (MUFU.EX2 + MUFU.RCP based, ~1e-7 rel err)
    return fmaf(2.f, sigf(2.f * x), -1.f);
}

// -------- prep: transpose weights to k-major, fuse biases --------
__global__ void prep_kernel(const float* __restrict__ W_ih, const float* __restrict__ W_hh,
                            const float* __restrict__ b_ih, const float* __restrict__ b_hh) {
    int k = blockIdx.x;
    for (int j = threadIdx.x; j < G4; j += blockDim.x) {
        float w = (k < EMB) ? W_ih[j * EMB + k] : W_hh[j * RDIM + (k - EMB)];
        g_Wt[k * G4 + j] = w;
        if (k == 0) g_bias[j] = b_ih[j] + b_hh[j];
    }
}

// -------- main persistent LSTM kernel --------
// SMEM layout (floats):
//  sAct [192][64]  : rows 0..63 = embeddings (rewritten/step), rows 64..191 = h (persistent)
//  sC   [128][64]  : cell state (persistent)
//  sW   [2][16*512]: double-buffered weight chunks
//  sX   [128]      : x staging (64 seq * 2)
//  sRed [64*8*5]   : output-head partial sums
//  sM   [64] (int) : mask staging
__global__ void __launch_bounds__(NTHREADS, 1)
lstm_kernel(const float* __restrict__ input_data,
            const float* __restrict__ h0,
            const float* __restrict__ c0,
            const int*   __restrict__ ped_mask,
            const float* __restrict__ W_emb,
            const float* __restrict__ b_emb,
            const float* __restrict__ W_out,
            const float* __restrict__ b_out,
            float* __restrict__ out_y,
            float* __restrict__ out_h,
            float* __restrict__ out_c)
{
    extern __shared__ float sm[];
    float* sAct = sm;                   // 12288 floats
    float* sC   = sm + 12288;           // 8192
    float* sW   = sm + 20480;           // 16384
    float* sX   = sm + 36864;           // 128
    float* sRed = sm + 36992;           // 2560
    int*   sM   = (int*)(sm + 39552);   // 64 ints

    const int t  = threadIdx.x;
    const int n0 = blockIdx.x * TILE;

    const int sb = t & 15;       // seq-block (4 seqs each)
    const int rb = t >> 4;       // 0..31 -> r0 = rb*4
    const uint32_t sWbase = (uint32_t)__cvta_generic_to_shared(sW);

    // ---- init h, c into SMEM ----
    {
        int s  = t >> 3;
        int r0 = (t & 7) << 4;
        #pragma unroll
        for (int i = 0; i < 16; i += 4) {
            float4 hv = *(const float4*)&h0[(size_t)(n0 + s) * RDIM + r0 + i];
            float4 cv = *(const float4*)&c0[(size_t)(n0 + s) * RDIM + r0 + i];
            sAct[(EMB + r0 + i + 0) * TILE + s] = hv.x;
            sAct[(EMB + r0 + i + 1) * TILE + s] = hv.y;
            sAct[(EMB + r0 + i + 2) * TILE + s] = hv.z;
            sAct[(EMB + r0 + i + 3) * TILE + s] = hv.w;
            sC[(r0 + i + 0) * TILE + s] = cv.x;
            sC[(r0 + i + 1) * TILE + s] = cv.y;
            sC[(r0 + i + 2) * TILE + s] = cv.z;
            sC[(r0 + i + 3) * TILE + s] = cv.w;
        }
    }

    #pragma unroll 1
    for (int st = 0; st < S_LEN; ++st) {
        __syncthreads();   // prev-step consumers done; safe to restage
        if (t < 128) {
            sX[t] = input_data[((size_t)st * N_SEQ + n0) * IN_DIM + t];
        } else if (t < 192) {
            sM[t - 128] = ped_mask[(size_t)st * N_SEQ + n0 + (t - 128)];
        }
        __syncthreads();

        // ---- prefetch weight chunk 0 (overlaps embedding) ----
        {
            const float4* src = (const float4*)(g_Wt);
            #pragma unroll
            for (int i = 0; i < 4; ++i) {
                int f = t + i * 512;
                cp_async16(sWbase + (uint32_t)f * 16u, src + f);
            }
            cp_commit();
        }

        // ---- embedding: e = relu(x @ W_emb^T + b_emb) -> sAct rows [0,64) ----
        {
            int s  = t & 63;
            int kb = (t >> 6) * 8;
            float x0 = sX[2 * s], x1 = sX[2 * s + 1];
            #pragma unroll
            for (int i = 0; i < 8; ++i) {
                int k = kb + i;
                float e = fmaf(W_emb[k * 2], x0, fmaf(W_emb[k * 2 + 1], x1, b_emb[k]));
                sAct[k * TILE + s] = fmaxf(e, 0.f);
            }
        }

        // ---- accumulators = fused bias (packed f32x2: gate pairs) ----
        unsigned long long acc[4][8];
        #pragma unroll
        for (int ty = 0; ty < 4; ++ty) {
            const unsigned long long* bp =
                (const unsigned long long*)&g_bias[ty * 128 + rb * 4];
            unsigned long long b0 = bp[0], b1 = bp[1];
            #pragma unroll
            for (int ss = 0; ss < 4; ++ss) { acc[ss][ty * 2] = b0; acc[ss][ty * 2 + 1] = b1; }
        }
        __syncthreads();   // embeddings visible

        // ---- gates GEMM: 12 chunks of K=16, cp.async double-buffered ----
        #pragma unroll 1
        for (int c = 0; c < NCHUNK; ++c) {
            cp_wait<0>();
            __syncthreads();      // everyone sees chunk c; prev reads of other buf done
            if (c + 1 < NCHUNK) {
                const float4* src = (const float4*)(g_Wt + (c + 1) * KC * G4);
                uint32_t dbase = sWbase + (uint32_t)(((c + 1) & 1) * (KC * G4)) * 4u;
                #pragma unroll
                for (int i = 0; i < 4; ++i) {
                    int f = t + i * 512;
                    cp_async16(dbase + (uint32_t)f * 16u, src + f);
                }
                cp_commit();
            }
            const float* wbuf = sW + (c & 1) * (KC * G4);
            #pragma unroll
            for (int kk = 0; kk < KC; ++kk) {
                int k = c * KC + kk;
                float4 a4 = *(const float4*)&sAct[k * TILE + sb * 4];
                unsigned long long da0 = dup2(a4.x), da1 = dup2(a4.y);
                unsigned long long da2 = dup2(a4.z), da3 = dup2(a4.w);
                #pragma unroll
                for (int ty = 0; ty < 4; ++ty) {
                    const unsigned long long* wp =
                        (const unsigned long long*)&wbuf[kk * G4 + ty * 128 + rb * 4];
                    unsigned long long w0 = wp[0], w1 = wp[1];
                    fma2(acc[0][ty * 2], da0, w0); fma2(acc[0][ty * 2 + 1], da0, w1);
                    fma2(acc[1][ty * 2], da1, w0); fma2(acc[1][ty * 2 + 1], da1, w1);
                    fma2(acc[2][ty * 2], da2, w0); fma2(acc[2][ty * 2 + 1], da2, w1);
                    fma2(acc[3][ty * 2], da3, w0); fma2(acc[3][ty * 2 + 1], da3, w1);
                }
            }
        }
        __syncthreads();   // all GEMM reads of sAct/h done before overwrite

        // ---- elementwise LSTM cell (gates live in regs) ----
        #pragma unroll
        for (int ss = 0; ss < 4; ++ss) {
            int s = sb * 4 + ss;
            int m = sM[s];
            float ga[4][4];
            #pragma unroll
            for (int ty = 0; ty < 4; ++ty) {
                float2 v0 = unpk(acc[ss][ty * 2]);
                float2 v1 = unpk(acc[ss][ty * 2 + 1]);
                ga[ty][0] = v0.x; ga[ty][1] = v0.y; ga[ty][2] = v1.x; ga[ty][3] = v1.y;
            }
            #pragma unroll
            for (int rr = 0; rr < 4; ++rr) {
                int r = rb * 4 + rr;
                float iv = sigf(ga[0][rr]);
                float fv = sigf(ga[1][rr]);
                float gv = tanh_(ga[2][rr]);
                float ov = sigf(ga[3][rr]);
                float cold = sC[r * TILE + s];
                float cnew = fmaf(fv, cold, iv * gv);
                float hnew = ov * tanh_(cnew);
                if (m) {
                    sC[r * TILE + s] = cnew;
                    sAct[(EMB + r) * TILE + s] = hnew;   // h_new == stored h when masked
                }
            }
        }
        __syncthreads();

        // ---- output head: out = mask ? h @ W_out^T + b_out : 0 ----
        {
            int s = t & 63;
            int part = t >> 6;  // 8 parts x 16 r
            float o0 = 0, o1 = 0, o2 = 0, o3 = 0, o4 = 0;
            #pragma unroll
            for (int rr = 0; rr < 16; ++rr) {
                int r = part * 16 + rr;
                float h = sAct[(EMB + r) * TILE + s];
                o0 = fmaf(h, W_out[0 * RDIM + r], o0);
                o1 = fmaf(h, W_out[1 * RDIM + r], o1);
                o2 = fmaf(h, W_out[2 * RDIM + r], o2);
                o3 = fmaf(h, W_out[3 * RDIM + r], o3);
                o4 = fmaf(h, W_out[4 * RDIM + r], o4);
            }
            float* rp = &sRed[(s * 8 + part) * 5];
            rp[0] = o0; rp[1] = o1; rp[2] = o2; rp[3] = o3; rp[4] = o4;
        }
        __syncthreads();
        if (t < 320) {
            int s = t / 5, o = t % 5;
            float a = 0.f;
            if (sM[s]) {
                #pragma unroll
                for (int p = 0; p < 8; ++p) a += sRed[(s * 8 + p) * 5 + o];
                a += b_out[o];
            }
            out_y[((size_t)st * N_SEQ + (n0 + s)) * OUT_DIM + o] = a;
        }
    }

    __syncthreads();
    // ---- final h, c writeback ----
    {
        int s  = t >> 3;
        int r0 = (t & 7) << 4;
        #pragma unroll
        for (int i = 0; i < 16; i += 4) {
            float4 hv, cv;
            hv.x = sAct[(EMB + r0 + i + 0) * TILE + s];
            hv.y = sAct[(EMB + r0 + i + 1) * TILE + s];
            hv.z = sAct[(EMB + r0 + i + 2) * TILE + s];
            hv.w = sAct[(EMB + r0 + i + 3) * TILE + s];
            cv.x = sC[(r0 + i + 0) * TILE + s];
            cv.y = sC[(r0 + i + 1) * TILE + s];
            cv.z = sC[(r0 + i + 2) * TILE + s];
            cv.w = sC[(r0 + i + 3) * TILE + s];
            *(float4*)&out_h[(size_t)(n0 + s) * RDIM + r0 + i] = hv;
            *(float4*)&out_c[(size_t)(n0 + s) * RDIM + r0 + i] = cv;
        }
    }
}

extern "C" void kernel_launch(void* const* d_in, const int* in_sizes, int n_in,
                              void* d_out, int out_size) {
    const float* input_data = (const float*)d_in[0];
    const float* h0         = (const float*)d_in[1];
    const float* c0         = (const float*)d_in[2];
    const int*   ped        = (const int*)  d_in[3];
    const float* W_emb      = (const float*)d_in[4];
    const float* b_emb      = (const float*)d_in[5];
    const float* W_ih       = (const float*)d_in[6];
    const float* W_hh       = (const float*)d_in[7];
    const float* b_ih       = (const float*)d_in[8];
    const float* b_hh       = (const float*)d_in[9];
    const float* W_out      = (const float*)d_in[10];
    const float* b_out      = (const float*)d_in[11];

    float* out   = (float*)d_out;
    float* out_y = out;                                      // [S][N][5]
    float* out_h = out + (size_t)S_LEN * N_SEQ * OUT_DIM;    // [N][128]
    float* out_c = out_h + (size_t)N_SEQ * RDIM;             // [N][128]

    prep_kernel<<<KDIM, 256>>>(W_ih, W_hh, b_ih, b_hh);

    const size_t SMEM = 158464;  // bytes
    cudaFuncSetAttribute(lstm_kernel, cudaFuncAttributeMaxDynamicSharedMemorySize, (int)SMEM);
    lstm_kernel<<<N_SEQ / TILE, NTHREADS, SMEM>>>(
        input_data, h0, c0, ped, W_emb, b_emb, W_out, b_out, out_y, out_h, out_c);
}

// round 5
// speedup vs baseline: 1.5795x; 1.5790x over previous
#include <cuda_runtime.h>
#include <cuda_bf16.h>
#include <cstdint>
#include <cstddef>

#define S_LEN   64
#define N_SEQ   65536
#define RDIM    128
#define OUT_DIM 5
#define TILE    128
#define NTHREADS 512
#define KDIM    192
#define NKC     12                      // k16 chunks per half
#define SLOTS_PER_STEP 24               // 2 halves x 12 kc
#define TOTAL_SLOTS (S_LEN * SLOTS_PER_STEP)   // 1536
#define SLOT_BYTES 16384                // hi p0/p1 + lo p0/p1, 4KB each
#define APITCH 384                      // A row pitch bytes (192 k * 2B)

// ---- SMEM offsets (bytes) ----
#define OFF_AHI   0          // 128*384 = 49152
#define OFF_ALO   49152
#define OFF_B     98304      // 3 x 16384
#define OFF_C     147456     // 128*128 f32 = 65536
#define OFF_RED   212992     // 2560 f32 = 10240
#define OFF_BIAS  223232     // 512 f32
#define OFF_WOUT  225280     // 640 f32
#define OFF_X     227840     // 256 f32
#define OFF_MASK  228864     // 128 i32
#define OFF_WEMB  229376     // 128 f32
#define OFF_BEMB  229888     // 64 f32
#define OFF_BOUT  230144     // 8 f32
#define SMEM_TOTAL 230400

// ---- device scratch ----
__device__ __align__(16) unsigned char g_Bstream[SLOTS_PER_STEP * SLOT_BYTES]; // 384KB
__device__ float g_bias[512];

// ---- helpers ----
__device__ __forceinline__ uint32_t pack2(float a, float b) {
    __nv_bfloat162 v(__float2bfloat16(a), __float2bfloat16(b));
    return *reinterpret_cast<uint32_t*>(&v);
}
__device__ __forceinline__ float bf_hi(float a) { return __bfloat162float(__float2bfloat16(a)); }

__device__ __forceinline__ float sigf(float x) { return __fdividef(1.f, 1.f + __expf(-x)); }
__device__ __forceinline__ float tanh_(float x) { return fmaf(2.f, sigf(2.f * x), -1.f); }

__device__ __forceinline__ void cp_async16(uint32_t smem_dst, const void* gsrc) {
    asm volatile("cp.async.cg.shared.global [%0], [%1], 16;" :: "r"(smem_dst), "l"(gsrc));
}
__device__ __forceinline__ void cp_commit() { asm volatile("cp.async.commit_group;"); }
template <int NW>
__device__ __forceinline__ void cp_wait() { asm volatile("cp.async.wait_group %0;" :: "n"(NW)); }

__device__ __forceinline__ void ldsm4(uint32_t* r, uint32_t addr) {
    asm volatile("ldmatrix.sync.aligned.m8n8.x4.shared.b16 {%0,%1,%2,%3}, [%4];"
        : "=r"(r[0]), "=r"(r[1]), "=r"(r[2]), "=r"(r[3]) : "r"(addr));
}
__device__ __forceinline__ void mma16816(float* c, const uint32_t* a, uint32_t b0, uint32_t b1) {
    asm volatile("mma.sync.aligned.m16n8k16.row.col.f32.bf16.bf16.f32 "
        "{%0,%1,%2,%3}, {%4,%5,%6,%7}, {%8,%9}, {%0,%1,%2,%3};"
        : "+f"(c[0]), "+f"(c[1]), "+f"(c[2]), "+f"(c[3])
        : "r"(a[0]), "r"(a[1]), "r"(a[2]), "r"(a[3]), "r"(b0), "r"(b1));
}

// A byte address with per-row XOR swizzle (conflict-free ldmatrix at pitch 384)
__device__ __forceinline__ uint32_t a_addr(uint32_t base, int m, int kb) {
    uint32_t kb16 = (uint32_t)kb & ~15u, off = (uint32_t)kb & 15u;
    return base + (uint32_t)m * APITCH + (kb16 ^ (((uint32_t)m & 7u) << 4)) + off;
}

// ---- prep: B stream. slot = nh*12+kc. Row j (0..255): r_local=j>>2, gate=j&3.
// Layout per slot: [0,4K) hi k0-7 | [4K,8K) hi k8-15 | [8K,12K) lo k0-7 | [12K,16K) lo k8-15
__global__ void prep_w(const float* __restrict__ Wih, const float* __restrict__ Whh) {
    int idx = blockIdx.x * 128 + threadIdx.x;      // 0..6143
    int slot = idx >> 8, j = idx & 255;
    int nh = slot / 12, kc = slot % 12;
    int gi = (j & 3) * 128 + nh * 64 + (j >> 2);
    uint32_t hi[8], lo[8];
    #pragma unroll
    for (int p = 0; p < 8; ++p) {
        int k0 = kc * 16 + p * 2;
        float w0 = (k0     < 64) ? Wih[gi * 64 + k0]     : Whh[gi * 128 + k0 - 64];
        float w1 = (k0 + 1 < 64) ? Wih[gi * 64 + k0 + 1] : Whh[gi * 128 + k0 + 1 - 64];
        hi[p] = pack2(w0, w1);
        lo[p] = pack2(w0 - bf_hi(w0), w1 - bf_hi(w1));
    }
    uint4* base = (uint4*)(g_Bstream + (size_t)slot * SLOT_BYTES + j * 16);
    base[0]          = make_uint4(hi[0], hi[1], hi[2], hi[3]);   // hi plane0
    base[4096 / 16]  = make_uint4(hi[4], hi[5], hi[6], hi[7]);   // hi plane1
    base[8192 / 16]  = make_uint4(lo[0], lo[1], lo[2], lo[3]);   // lo plane0
    base[12288 / 16] = make_uint4(lo[4], lo[5], lo[6], lo[7]);   // lo plane1
}
__global__ void prep_bias(const float* __restrict__ bih, const float* __restrict__ bhh) {
    int t = threadIdx.x; g_bias[t] = bih[t] + bhh[t];
}

// ---- main kernel ----
__global__ void __launch_bounds__(NTHREADS, 1)
lstm_mma(const float* __restrict__ input_data,
         const float* __restrict__ h0,
         const float* __restrict__ c0,
         const int*   __restrict__ ped_mask,
         const float* __restrict__ W_emb,
         const float* __restrict__ b_emb,
         const float* __restrict__ W_out,
         const float* __restrict__ b_out,
         float* __restrict__ out_y,
         float* __restrict__ out_h,
         float* __restrict__ out_c)
{
    extern __shared__ unsigned char smem[];
    const uint32_t sbase = (uint32_t)__cvta_generic_to_shared(smem);
    const int t = threadIdx.x, lane = t & 31, wid = t >> 5;
    const int warp_m = wid >> 2, warp_n = wid & 3;
    const int n0 = blockIdx.x * TILE;

    float* sC    = (float*)(smem + OFF_C);
    float* sRed  = (float*)(smem + OFF_RED);
    float* sBias = (float*)(smem + OFF_BIAS);
    float* sWout = (float*)(smem + OFF_WOUT);
    float* sX    = (float*)(smem + OFF_X);
    int*   sMask = (int*)  (smem + OFF_MASK);
    float* sWemb = (float*)(smem + OFF_WEMB);
    float* sBemb = (float*)(smem + OFF_BEMB);
    float* sBout = (float*)(smem + OFF_BOUT);

    // stage constants
    sBias[t] = g_bias[t];
    for (int i = t; i < 640; i += NTHREADS) sWout[i] = W_out[i];
    if (t < 128) sWemb[t] = W_emb[t];
    if (t < 64)  sBemb[t] = b_emb[t];
    if (t < 5)   sBout[t] = b_out[t];

    // init h -> A (bf16 hi/lo), c -> sC
    {
        int m = t >> 2, rblk = (t & 3) * 32;
        const float4* hp = (const float4*)&h0[(size_t)(n0 + m) * RDIM + rblk];
        const float4* cp = (const float4*)&c0[(size_t)(n0 + m) * RDIM + rblk];
        #pragma unroll
        for (int jj = 0; jj < 8; ++jj) {
            float4 hv = hp[jj], cv = cp[jj];
            *(float4*)&sC[m * 128 + rblk + jj * 4] = cv;
            int r0 = rblk + jj * 4;
            uint32_t aH0 = a_addr(sbase + OFF_AHI, m, 128 + 2 * r0);
            uint32_t aH1 = a_addr(sbase + OFF_AHI, m, 128 + 2 * r0 + 4);
            uint32_t aL0 = a_addr(sbase + OFF_ALO, m, 128 + 2 * r0);
            uint32_t aL1 = a_addr(sbase + OFF_ALO, m, 128 + 2 * r0 + 4);
            uint32_t vh0 = pack2(hv.x, hv.y), vh1 = pack2(hv.z, hv.w);
            uint32_t vl0 = pack2(hv.x - bf_hi(hv.x), hv.y - bf_hi(hv.y));
            uint32_t vl1 = pack2(hv.z - bf_hi(hv.z), hv.w - bf_hi(hv.w));
            asm volatile("st.shared.b32 [%0], %1;" :: "r"(aH0), "r"(vh0));
            asm volatile("st.shared.b32 [%0], %1;" :: "r"(aH1), "r"(vh1));
            asm volatile("st.shared.b32 [%0], %1;" :: "r"(aL0), "r"(vl0));
            asm volatile("st.shared.b32 [%0], %1;" :: "r"(aL1), "r"(vl1));
        }
    }

    // prologue: slots 0,1 in flight
    {
        uint32_t d0 = sbase + OFF_B;
        cp_async16(d0 + t * 16u, g_Bstream + t * 16);
        cp_async16(d0 + (t + 512) * 16u, g_Bstream + (size_t)(t + 512) * 16);
        cp_commit();
        uint32_t d1 = sbase + OFF_B + SLOT_BYTES;
        cp_async16(d1 + t * 16u, g_Bstream + SLOT_BYTES + t * 16);
        cp_async16(d1 + (t + 512) * 16u, g_Bstream + SLOT_BYTES + (size_t)(t + 512) * 16);
        cp_commit();
    }
    __syncthreads();

    float hpend[16];

    #pragma unroll 1
    for (int st = 0; st < S_LEN; ++st) {
        // stage x, mask
        if (t < 64) {
            ((float4*)sX)[t] = ((const float4*)(input_data + ((size_t)st * N_SEQ + n0) * 2))[t];
        } else if (t < 96) {
            ((int4*)sMask)[t - 64] = ((const int4*)(ped_mask + (size_t)st * N_SEQ + n0))[t - 64];
        }
        __syncthreads();

        // embedding -> A cols 0..63 (hi/lo)
        {
            int kp = lane;             // k-pair 0..31
            int sg = wid;              // 8 seqs each
            float w00 = sWemb[kp * 4], w01 = sWemb[kp * 4 + 1];
            float w10 = sWemb[kp * 4 + 2], w11 = sWemb[kp * 4 + 3];
            float bb0 = sBemb[kp * 2], bb1 = sBemb[kp * 2 + 1];
            #pragma unroll
            for (int q = 0; q < 8; ++q) {
                int s2 = sg * 8 + q;
                float x0 = sX[s2 * 2], x1 = sX[s2 * 2 + 1];
                float e0 = fmaxf(fmaf(w00, x0, fmaf(w01, x1, bb0)), 0.f);
                float e1 = fmaxf(fmaf(w10, x0, fmaf(w11, x1, bb1)), 0.f);
                uint32_t aH = a_addr(sbase + OFF_AHI, s2, kp * 4);
                uint32_t aL = a_addr(sbase + OFF_ALO, s2, kp * 4);
                uint32_t vh = pack2(e0, e1);
                uint32_t vl = pack2(e0 - bf_hi(e0), e1 - bf_hi(e1));
                asm volatile("st.shared.b32 [%0], %1;" :: "r"(aH), "r"(vh));
                asm volatile("st.shared.b32 [%0], %1;" :: "r"(aL), "r"(vl));
            }
        }

        // ---- two halves: gates for r in [nh*64, nh*64+64) ----
        #pragma unroll 1
        for (int nh = 0; nh < 2; ++nh) {
            float acc[2][8][4];
            #pragma unroll
            for (int a = 0; a < 2; ++a)
                #pragma unroll
                for (int b = 0; b < 8; ++b)
                    #pragma unroll
                    for (int d = 0; d < 4; ++d) acc[a][b][d] = 0.f;

            #pragma unroll 1
            for (int kc = 0; kc < NKC; ++kc) {
                int g = st * SLOTS_PER_STEP + nh * NKC + kc;
                if (g + 1 < TOTAL_SLOTS) cp_wait<1>(); else cp_wait<0>();
                __syncthreads();
                int q = g + 2;
                if (q < TOTAL_SLOTS) {
                    const unsigned char* src = g_Bstream + (size_t)(q % SLOTS_PER_STEP) * SLOT_BYTES;
                    uint32_t dst = sbase + OFF_B + (uint32_t)(q % 3) * SLOT_BYTES;
                    cp_async16(dst + t * 16u, src + t * 16);
                    cp_async16(dst + (t + 512) * 16u, src + (size_t)(t + 512) * 16);
                    cp_commit();
                }
                uint32_t sbuf = sbase + OFF_B + (uint32_t)(g % 3) * SLOT_BYTES;

                // A fragments (hi & lo) for 2 m-tiles
                uint32_t ah[2][4], al[2][4];
                int arow = warp_m * 32 + (lane & 15);
                int akb  = kc * 32 + ((lane >> 4) << 4);
                #pragma unroll
                for (int mt = 0; mt < 2; ++mt) {
                    ldsm4(ah[mt], a_addr(sbase + OFF_AHI, arow + mt * 16, akb));
                    ldsm4(al[mt], a_addr(sbase + OFF_ALO, arow + mt * 16, akb));
                }
                // B: 4 pairs of n8-tiles
                int msel = lane >> 3, r8 = lane & 7;
                uint32_t brow_off = (uint32_t)(warp_n * 64 + ((msel >> 1) << 3) + r8) * 16u
                                  + (uint32_t)(msel & 1) * 4096u;
                #pragma unroll
                for (int p = 0; p < 4; ++p) {
                    uint32_t bh[4], bl[4];
                    uint32_t ba = sbuf + brow_off + (uint32_t)p * 256u;  // p*16 rows * 16B
                    ldsm4(bh, ba);
                    #pragma unroll
                    for (int mt = 0; mt < 2; ++mt) {
                        mma16816(acc[mt][2 * p],     ah[mt], bh[0], bh[1]);
                        mma16816(acc[mt][2 * p + 1], ah[mt], bh[2], bh[3]);
                        mma16816(acc[mt][2 * p],     al[mt], bh[0], bh[1]);
                        mma16816(acc[mt][2 * p + 1], al[mt], bh[2], bh[3]);
                    }
                    ldsm4(bl, ba + 8192u);
                    #pragma unroll
                    for (int mt = 0; mt < 2; ++mt) {
                        mma16816(acc[mt][2 * p],     ah[mt], bl[0], bl[1]);
                        mma16816(acc[mt][2 * p + 1], ah[mt], bl[2], bl[3]);
                    }
                }
            }

            // ---- cell for this half ----
            const int odd = lane & 1;
            #pragma unroll
            for (int mt = 0; mt < 2; ++mt) {
                #pragma unroll
                for (int nt = 0; nt < 8; ++nt) {
                    float c0 = acc[mt][nt][0], c1 = acc[mt][nt][1];
                    float c2 = acc[mt][nt][2], c3 = acc[mt][nt][3];
                    float e0 = __shfl_xor_sync(0xffffffffu, c0, 1);
                    float e1 = __shfl_xor_sync(0xffffffffu, c1, 1);
                    float e2 = __shfl_xor_sync(0xffffffffu, c2, 1);
                    float e3 = __shfl_xor_sync(0xffffffffu, c3, 1);
                    int mrow = warp_m * 32 + mt * 16 + (lane >> 2) + (odd ? 8 : 0);
                    int rl   = warp_n * 16 + nt * 2 + ((lane & 3) >> 1);
                    int r    = nh * 64 + rl;
                    float zi = odd ? e2 : c0;
                    float zf = odd ? e3 : c1;
                    float zg = odd ? c2 : e0;
                    float zo = odd ? c3 : e1;
                    zi += sBias[r]; zf += sBias[128 + r];
                    zg += sBias[256 + r]; zo += sBias[384 + r];
                    float co = sC[mrow * 128 + r];
                    float cn = fmaf(sigf(zf), co, sigf(zi) * tanh_(zg));
                    float hn = sigf(zo) * tanh_(cn);
                    int msk = sMask[mrow];
                    if (msk) sC[mrow * 128 + r] = cn;
                    if (nh == 0) {
                        hpend[mt * 8 + nt] = hn;
                    } else if (msk) {
                        uint32_t aH = a_addr(sbase + OFF_AHI, mrow, 128 + 2 * r);
                        uint32_t aL = a_addr(sbase + OFF_ALO, mrow, 128 + 2 * r);
                        __nv_bfloat16 bh16 = __float2bfloat16(hn);
                        __nv_bfloat16 bl16 = __float2bfloat16(hn - __bfloat162float(bh16));
                        asm volatile("st.shared.b16 [%0], %1;" :: "r"(aH), "h"(*(uint16_t*)&bh16));
                        asm volatile("st.shared.b16 [%0], %1;" :: "r"(aL), "h"(*(uint16_t*)&bl16));
                    }
                }
            }
        }

        // flush pending half-0 h writes (GEMMs done reading A)
        #pragma unroll
        for (int mt = 0; mt < 2; ++mt) {
            #pragma unroll
            for (int nt = 0; nt < 8; ++nt) {
                int mrow = warp_m * 32 + mt * 16 + (lane >> 2) + ((lane & 1) ? 8 : 0);
                int r    = warp_n * 16 + nt * 2 + ((lane & 3) >> 1);
                if (sMask[mrow]) {
                    float hn = hpend[mt * 8 + nt];
                    uint32_t aH = a_addr(sbase + OFF_AHI, mrow, 128 + 2 * r);
                    uint32_t aL = a_addr(sbase + OFF_ALO, mrow, 128 + 2 * r);
                    __nv_bfloat16 bh16 = __float2bfloat16(hn);
                    __nv_bfloat16 bl16 = __float2bfloat16(hn - __bfloat162float(bh16));
                    asm volatile("st.shared.b16 [%0], %1;" :: "r"(aH), "h"(*(uint16_t*)&bh16));
                    asm volatile("st.shared.b16 [%0], %1;" :: "r"(aL), "h"(*(uint16_t*)&bl16));
                }
            }
        }
        __syncthreads();

        // ---- output head ----
        {
            int s = t & 127, part = t >> 7;    // 4 parts x 32 r
            float o0 = 0, o1 = 0, o2 = 0, o3 = 0, o4 = 0;
            #pragma unroll
            for (int rr = 0; rr < 16; ++rr) {
                int r0 = part * 32 + rr * 2;
                uint32_t aH = a_addr(sbase + OFF_AHI, s, 128 + 2 * r0);
                uint32_t aL = a_addr(sbase + OFF_ALO, s, 128 + 2 * r0);
                uint32_t vh, vl;
                asm volatile("ld.shared.b32 %0, [%1];" : "=r"(vh) : "r"(aH));
                asm volatile("ld.shared.b32 %0, [%1];" : "=r"(vl) : "r"(aL));
                __nv_bfloat162 h2 = *reinterpret_cast<__nv_bfloat162*>(&vh);
                __nv_bfloat162 l2 = *reinterpret_cast<__nv_bfloat162*>(&vl);
                float ha = __bfloat162float(h2.x) + __bfloat162float(l2.x);
                float hb = __bfloat162float(h2.y) + __bfloat162float(l2.y);
                o0 = fmaf(ha, sWout[r0], fmaf(hb, sWout[r0 + 1], o0));
                o1 = fmaf(ha, sWout[128 + r0], fmaf(hb, sWout[128 + r0 + 1], o1));
                o2 = fmaf(ha, sWout[256 + r0], fmaf(hb, sWout[256 + r0 + 1], o2));
                o3 = fmaf(ha, sWout[384 + r0], fmaf(hb, sWout[384 + r0 + 1], o3));
                o4 = fmaf(ha, sWout[512 + r0], fmaf(hb, sWout[512 + r0 + 1], o4));
            }
            float* rp = &sRed[(s * 4 + part) * 5];
            rp[0] = o0; rp[1] = o1; rp[2] = o2; rp[3] = o3; rp[4] = o4;
        }
        __syncthreads();
        for (int idx = t; idx < 640; idx += NTHREADS) {
            int s2 = idx / 5, oo = idx % 5;
            float v = 0.f;
            if (sMask[s2]) {
                v = sRed[(s2 * 4 + 0) * 5 + oo] + sRed[(s2 * 4 + 1) * 5 + oo]
                  + sRed[(s2 * 4 + 2) * 5 + oo] + sRed[(s2 * 4 + 3) * 5 + oo] + sBout[oo];
            }
            out_y[((size_t)st * N_SEQ + n0 + s2) * OUT_DIM + oo] = v;
        }
        __syncthreads();
    }

    // ---- final h, c writeback ----
    {
        int m = t >> 2, rblk = (t & 3) * 32;
        float4* hp = (float4*)&out_h[(size_t)(n0 + m) * RDIM + rblk];
        float4* cp = (float4*)&out_c[(size_t)(n0 + m) * RDIM + rblk];
        #pragma unroll
        for (int jj = 0; jj < 8; ++jj) {
            int r0 = rblk + jj * 4;
            uint32_t vh0, vh1, vl0, vl1;
            uint32_t aH0 = a_addr(sbase + OFF_AHI, m, 128 + 2 * r0);
            uint32_t aH1 = a_addr(sbase + OFF_AHI, m, 128 + 2 * r0 + 4);
            uint32_t aL0 = a_addr(sbase + OFF_ALO, m, 128 + 2 * r0);
            uint32_t aL1 = a_addr(sbase + OFF_ALO, m, 128 + 2 * r0 + 4);
            asm volatile("ld.shared.b32 %0, [%1];" : "=r"(vh0) : "r"(aH0));
            asm volatile("ld.shared.b32 %0, [%1];" : "=r"(vh1) : "r"(aH1));
            asm volatile("ld.shared.b32 %0, [%1];" : "=r"(vl0) : "r"(aL0));
            asm volatile("ld.shared.b32 %0, [%1];" : "=r"(vl1) : "r"(aL1));
            __nv_bfloat162 h2a = *reinterpret_cast<__nv_bfloat162*>(&vh0);
            __nv_bfloat162 h2b = *reinterpret_cast<__nv_bfloat162*>(&vh1);
            __nv_bfloat162 l2a = *reinterpret_cast<__nv_bfloat162*>(&vl0);
            __nv_bfloat162 l2b = *reinterpret_cast<__nv_bfloat162*>(&vl1);
            float4 hv;
            hv.x = __bfloat162float(h2a.x) + __bfloat162float(l2a.x);
            hv.y = __bfloat162float(h2a.y) + __bfloat162float(l2a.y);
            hv.z = __bfloat162float(h2b.x) + __bfloat162float(l2b.x);
            hv.w = __bfloat162float(h2b.y) + __bfloat162float(l2b.y);
            hp[jj] = hv;
            cp[jj] = *(float4*)&sC[m * 128 + r0];
        }
    }
}

extern "C" void kernel_launch(void* const* d_in, const int* in_sizes, int n_in,
                              void* d_out, int out_size) {
    const float* input_data = (const float*)d_in[0];
    const float* h0         = (const float*)d_in[1];
    const float* c0         = (const float*)d_in[2];
    const int*   ped        = (const int*)  d_in[3];
    const float* W_emb      = (const float*)d_in[4];
    const float* b_emb      = (const float*)d_in[5];
    const float* W_ih       = (const float*)d_in[6];
    const float* W_hh       = (const float*)d_in[7];
    const float* b_ih       = (const float*)d_in[8];
    const float* b_hh       = (const float*)d_in[9];
    const float* W_out      = (const float*)d_in[10];
    const float* b_out      = (const float*)d_in[11];

    float* out   = (float*)d_out;
    float* out_y = out;                                      // [S][N][5]
    float* out_h = out + (size_t)S_LEN * N_SEQ * OUT_DIM;    // [N][128]
    float* out_c = out_h + (size_t)N_SEQ * RDIM;             // [N][128]

    prep_w<<<48, 128>>>(W_ih, W_hh);
    prep_bias<<<1, 512>>>(b_ih, b_hh);

    cudaFuncSetAttribute(lstm_mma, cudaFuncAttributeMaxDynamicSharedMemorySize, SMEM_TOTAL);
    lstm_mma<<<N_SEQ / TILE, NTHREADS, SMEM_TOTAL>>>(
        input_data, h0, c0, ped, W_emb, b_emb, W_out, b_out, out_y, out_h, out_c);
}

// round 6
// speedup vs baseline: 1.8941x; 1.1992x over previous
#include <cuda_runtime.h>
#include <cuda_fp16.h>
#include <cstdint>
#include <cstddef>

#define S_LEN   64
#define N_SEQ   65536
#define RDIM    128
#define OUT_DIM 5
#define TILE    128
#define NTHREADS 512
#define KDIM    192
#define NKC     12                      // k16 chunks per half
#define SLOTS_PER_STEP 24               // 2 halves x 12 kc
#define TOTAL_SLOTS (S_LEN * SLOTS_PER_STEP)   // 1536
#define SLOT_BYTES 8192                 // fp16 hi only: plane0 (k0-7) + plane1 (k8-15)
#define NBUF 4
#define APITCH 384                      // A row pitch bytes (192 k * 2B)

// ---- SMEM offsets (bytes) ----
#define OFF_AHI   0          // 128*384 = 49152
#define OFF_ALO   49152
#define OFF_B     98304      // 4 x 8192 = 32768
#define OFF_C     131072     // 128*128 f32 = 65536
#define OFF_RED   196608     // 2560 f32 = 10240
#define OFF_BIAS  206848     // 512 f32
#define OFF_WOUT  208896     // 640 f32 -> 2560
#define OFF_X     211456     // 256 f32
#define OFF_MASK  212480     // 128 i32
#define OFF_WEMB  212992     // 128 f32
#define OFF_BEMB  213504     // 64 f32
#define OFF_BOUT  213760     // 8 f32
#define SMEM_TOTAL 213792

// ---- device scratch ----
__device__ __align__(16) unsigned char g_Bstream[SLOTS_PER_STEP * SLOT_BYTES]; // 192KB
__device__ float g_bias[512];

// ---- helpers ----
__device__ __forceinline__ uint32_t pack2h(float a, float b) {
    __half2 v = __floats2half2_rn(a, b);
    return *reinterpret_cast<uint32_t*>(&v);
}
__device__ __forceinline__ float h_hi(float a) { return __half2float(__float2half_rn(a)); }

__device__ __forceinline__ float sigf(float x) { return __fdividef(1.f, 1.f + __expf(-x)); }
__device__ __forceinline__ float tanh_(float x) { return fmaf(2.f, sigf(2.f * x), -1.f); }

__device__ __forceinline__ void cp_async16(uint32_t smem_dst, const void* gsrc) {
    asm volatile("cp.async.cg.shared.global [%0], [%1], 16;" :: "r"(smem_dst), "l"(gsrc));
}
__device__ __forceinline__ void cp_commit() { asm volatile("cp.async.commit_group;"); }
__device__ __forceinline__ void cp_wait_n(int n) {
    if (n >= 2)      asm volatile("cp.async.wait_group 2;");
    else if (n == 1) asm volatile("cp.async.wait_group 1;");
    else             asm volatile("cp.async.wait_group 0;");
}

__device__ __forceinline__ void ldsm4(uint32_t* r, uint32_t addr) {
    asm volatile("ldmatrix.sync.aligned.m8n8.x4.shared.b16 {%0,%1,%2,%3}, [%4];"
        : "=r"(r[0]), "=r"(r[1]), "=r"(r[2]), "=r"(r[3]) : "r"(addr));
}
__device__ __forceinline__ void mma16816h(float* c, const uint32_t* a, uint32_t b0, uint32_t b1) {
    asm volatile("mma.sync.aligned.m16n8k16.row.col.f32.f16.f16.f32 "
        "{%0,%1,%2,%3}, {%4,%5,%6,%7}, {%8,%9}, {%0,%1,%2,%3};"
        : "+f"(c[0]), "+f"(c[1]), "+f"(c[2]), "+f"(c[3])
        : "r"(a[0]), "r"(a[1]), "r"(a[2]), "r"(a[3]), "r"(b0), "r"(b1));
}

// A byte address with per-row XOR swizzle (conflict-free ldmatrix at pitch 384)
__device__ __forceinline__ uint32_t a_addr(uint32_t base, int m, int kb) {
    uint32_t kb16 = (uint32_t)kb & ~15u, off = (uint32_t)kb & 15u;
    return base + (uint32_t)m * APITCH + (kb16 ^ (((uint32_t)m & 7u) << 4)) + off;
}

// ---- prep: B stream, fp16. slot = nh*12+kc. Row j (0..255): r_local=j>>2, gate=j&3.
// Layout per slot: [0,4K) k0-7 | [4K,8K) k8-15
__global__ void prep_w(const float* __restrict__ Wih, const float* __restrict__ Whh) {
    int idx = blockIdx.x * 128 + threadIdx.x;      // 0..6143
    int slot = idx >> 8, j = idx & 255;
    int nh = slot / 12, kc = slot % 12;
    int gi = (j & 3) * 128 + nh * 64 + (j >> 2);
    uint32_t hi[8];
    #pragma unroll
    for (int p = 0; p < 8; ++p) {
        int k0 = kc * 16 + p * 2;
        float w0 = (k0     < 64) ? Wih[gi * 64 + k0]     : Whh[gi * 128 + k0 - 64];
        float w1 = (k0 + 1 < 64) ? Wih[gi * 64 + k0 + 1] : Whh[gi * 128 + k0 + 1 - 64];
        hi[p] = pack2h(w0, w1);
    }
    uint4* base = (uint4*)(g_Bstream + (size_t)slot * SLOT_BYTES + j * 16);
    base[0]         = make_uint4(hi[0], hi[1], hi[2], hi[3]);   // plane0
    base[4096 / 16] = make_uint4(hi[4], hi[5], hi[6], hi[7]);   // plane1
}
__global__ void prep_bias(const float* __restrict__ bih, const float* __restrict__ bhh) {
    int t = threadIdx.x; g_bias[t] = bih[t] + bhh[t];
}

// ---- main kernel ----
__global__ void __launch_bounds__(NTHREADS, 1)
lstm_mma(const float* __restrict__ input_data,
         const float* __restrict__ h0,
         const float* __restrict__ c0,
         const int*   __restrict__ ped_mask,
         const float* __restrict__ W_emb,
         const float* __restrict__ b_emb,
         const float* __restrict__ W_out,
         const float* __restrict__ b_out,
         float* __restrict__ out_y,
         float* __restrict__ out_h,
         float* __restrict__ out_c)
{
    extern __shared__ unsigned char smem[];
    const uint32_t sbase = (uint32_t)__cvta_generic_to_shared(smem);
    const int t = threadIdx.x, lane = t & 31, wid = t >> 5;
    const int warp_m = wid >> 2, warp_n = wid & 3;
    const int n0 = blockIdx.x * TILE;

    float* sC    = (float*)(smem + OFF_C);
    float* sRed  = (float*)(smem + OFF_RED);
    float* sBias = (float*)(smem + OFF_BIAS);
    float* sWout = (float*)(smem + OFF_WOUT);
    float* sX    = (float*)(smem + OFF_X);
    int*   sMask = (int*)  (smem + OFF_MASK);
    float* sWemb = (float*)(smem + OFF_WEMB);
    float* sBemb = (float*)(smem + OFF_BEMB);
    float* sBout = (float*)(smem + OFF_BOUT);

    // stage constants
    sBias[t] = g_bias[t];
    for (int i = t; i < 640; i += NTHREADS) sWout[i] = W_out[i];
    if (t < 128) sWemb[t] = W_emb[t];
    if (t < 64)  sBemb[t] = b_emb[t];
    if (t < 5)   sBout[t] = b_out[t];

    // init h -> A (fp16 hi/lo), c -> sC
    {
        int m = t >> 2, rblk = (t & 3) * 32;
        const float4* hp = (const float4*)&h0[(size_t)(n0 + m) * RDIM + rblk];
        const float4* cp = (const float4*)&c0[(size_t)(n0 + m) * RDIM + rblk];
        #pragma unroll
        for (int jj = 0; jj < 8; ++jj) {
            float4 hv = hp[jj], cv = cp[jj];
            *(float4*)&sC[m * 128 + rblk + jj * 4] = cv;
            int r0 = rblk + jj * 4;
            uint32_t aH0 = a_addr(sbase + OFF_AHI, m, 128 + 2 * r0);
            uint32_t aH1 = a_addr(sbase + OFF_AHI, m, 128 + 2 * r0 + 4);
            uint32_t aL0 = a_addr(sbase + OFF_ALO, m, 128 + 2 * r0);
            uint32_t aL1 = a_addr(sbase + OFF_ALO, m, 128 + 2 * r0 + 4);
            uint32_t vh0 = pack2h(hv.x, hv.y), vh1 = pack2h(hv.z, hv.w);
            uint32_t vl0 = pack2h(hv.x - h_hi(hv.x), hv.y - h_hi(hv.y));
            uint32_t vl1 = pack2h(hv.z - h_hi(hv.z), hv.w - h_hi(hv.w));
            asm volatile("st.shared.b32 [%0], %1;" :: "r"(aH0), "r"(vh0));
            asm volatile("st.shared.b32 [%0], %1;" :: "r"(aH1), "r"(vh1));
            asm volatile("st.shared.b32 [%0], %1;" :: "r"(aL0), "r"(vl0));
            asm volatile("st.shared.b32 [%0], %1;" :: "r"(aL1), "r"(vl1));
        }
    }

    // prologue: slots 0,1,2 in flight (1 cp16 per thread per slot: 8KB)
    #pragma unroll
    for (int s = 0; s < 3; ++s) {
        cp_async16(sbase + OFF_B + (uint32_t)s * SLOT_BYTES + t * 16u,
                   g_Bstream + (size_t)s * SLOT_BYTES + t * 16);
        cp_commit();
    }
    __syncthreads();

    float hpend[16];

    #pragma unroll 1
    for (int st = 0; st < S_LEN; ++st) {
        // stage x, mask
        if (t < 64) {
            ((float4*)sX)[t] = ((const float4*)(input_data + ((size_t)st * N_SEQ + n0) * 2))[t];
        } else if (t < 96) {
            ((int4*)sMask)[t - 64] = ((const int4*)(ped_mask + (size_t)st * N_SEQ + n0))[t - 64];
        }
        __syncthreads();

        // embedding -> A cols 0..63 (fp16 hi/lo)
        {
            int kp = lane, sg = wid;
            float w00 = sWemb[kp * 4], w01 = sWemb[kp * 4 + 1];
            float w10 = sWemb[kp * 4 + 2], w11 = sWemb[kp * 4 + 3];
            float bb0 = sBemb[kp * 2], bb1 = sBemb[kp * 2 + 1];
            #pragma unroll
            for (int q = 0; q < 8; ++q) {
                int s2 = sg * 8 + q;
                float x0 = sX[s2 * 2], x1 = sX[s2 * 2 + 1];
                float e0 = fmaxf(fmaf(w00, x0, fmaf(w01, x1, bb0)), 0.f);
                float e1 = fmaxf(fmaf(w10, x0, fmaf(w11, x1, bb1)), 0.f);
                uint32_t aH = a_addr(sbase + OFF_AHI, s2, kp * 4);
                uint32_t aL = a_addr(sbase + OFF_ALO, s2, kp * 4);
                uint32_t vh = pack2h(e0, e1);
                uint32_t vl = pack2h(e0 - h_hi(e0), e1 - h_hi(e1));
                asm volatile("st.shared.b32 [%0], %1;" :: "r"(aH), "r"(vh));
                asm volatile("st.shared.b32 [%0], %1;" :: "r"(aL), "r"(vl));
            }
        }

        // ---- two halves: gates for r in [nh*64, nh*64+64) ----
        #pragma unroll 1
        for (int nh = 0; nh < 2; ++nh) {
            float acc[2][8][4];
            #pragma unroll
            for (int a = 0; a < 2; ++a)
                #pragma unroll
                for (int b = 0; b < 8; ++b)
                    #pragma unroll
                    for (int d = 0; d < 4; ++d) acc[a][b][d] = 0.f;

            #pragma unroll 1
            for (int kc = 0; kc < NKC; ++kc) {
                int g = st * SLOTS_PER_STEP + nh * NKC + kc;
                int rem = TOTAL_SLOTS - 1 - g;
                cp_wait_n(rem < 2 ? rem : 2);
                __syncthreads();
                int q = g + 3;
                if (q < TOTAL_SLOTS) {
                    cp_async16(sbase + OFF_B + (uint32_t)(q % NBUF) * SLOT_BYTES + t * 16u,
                               g_Bstream + (size_t)(q % SLOTS_PER_STEP) * SLOT_BYTES + t * 16);
                    cp_commit();
                }
                uint32_t sbuf = sbase + OFF_B + (uint32_t)(g % NBUF) * SLOT_BYTES;

                // A fragments (hi & lo) for 2 m-tiles
                uint32_t ah[2][4], al[2][4];
                int arow = warp_m * 32 + (lane & 15);
                int akb  = kc * 32 + ((lane >> 4) << 4);
                #pragma unroll
                for (int mt = 0; mt < 2; ++mt) {
                    ldsm4(ah[mt], a_addr(sbase + OFF_AHI, arow + mt * 16, akb));
                    ldsm4(al[mt], a_addr(sbase + OFF_ALO, arow + mt * 16, akb));
                }
                // B: 4 pairs of n8-tiles (hi only)
                int msel = lane >> 3, r8 = lane & 7;
                uint32_t brow_off = (uint32_t)(warp_n * 64 + ((msel >> 1) << 3) + r8) * 16u
                                  + (uint32_t)(msel & 1) * 4096u;
                #pragma unroll
                for (int p = 0; p < 4; ++p) {
                    uint32_t bh[4];
                    uint32_t ba = sbuf + brow_off + (uint32_t)p * 256u;
                    ldsm4(bh, ba);
                    #pragma unroll
                    for (int mt = 0; mt < 2; ++mt) {
                        mma16816h(acc[mt][2 * p],     ah[mt], bh[0], bh[1]);
                        mma16816h(acc[mt][2 * p + 1], ah[mt], bh[2], bh[3]);
                        mma16816h(acc[mt][2 * p],     al[mt], bh[0], bh[1]);
                        mma16816h(acc[mt][2 * p + 1], al[mt], bh[2], bh[3]);
                    }
                }
            }

            // ---- cell for this half ----
            const int odd = lane & 1;
            #pragma unroll
            for (int mt = 0; mt < 2; ++mt) {
                #pragma unroll
                for (int nt = 0; nt < 8; ++nt) {
                    float c0 = acc[mt][nt][0], c1 = acc[mt][nt][1];
                    float c2 = acc[mt][nt][2], c3 = acc[mt][nt][3];
                    float e0 = __shfl_xor_sync(0xffffffffu, c0, 1);
                    float e1 = __shfl_xor_sync(0xffffffffu, c1, 1);
                    float e2 = __shfl_xor_sync(0xffffffffu, c2, 1);
                    float e3 = __shfl_xor_sync(0xffffffffu, c3, 1);
                    int mrow = warp_m * 32 + mt * 16 + (lane >> 2) + (odd ? 8 : 0);
                    int rl   = warp_n * 16 + nt * 2 + ((lane & 3) >> 1);
                    int r    = nh * 64 + rl;
                    float zi = odd ? e2 : c0;
                    float zf = odd ? e3 : c1;
                    float zg = odd ? c2 : e0;
                    float zo = odd ? c3 : e1;
                    zi += sBias[r]; zf += sBias[128 + r];
                    zg += sBias[256 + r]; zo += sBias[384 + r];
                    float co = sC[mrow * 128 + r];
                    float cn = fmaf(sigf(zf), co, sigf(zi) * tanh_(zg));
                    float hn = sigf(zo) * tanh_(cn);
                    int msk = sMask[mrow];
                    if (msk) sC[mrow * 128 + r] = cn;
                    if (nh == 0) {
                        hpend[mt * 8 + nt] = hn;
                    } else if (msk) {
                        uint32_t aH = a_addr(sbase + OFF_AHI, mrow, 128 + 2 * r);
                        uint32_t aL = a_addr(sbase + OFF_ALO, mrow, 128 + 2 * r);
                        __half bh16 = __float2half_rn(hn);
                        __half bl16 = __float2half_rn(hn - __half2float(bh16));
                        asm volatile("st.shared.b16 [%0], %1;" :: "r"(aH), "h"(*(uint16_t*)&bh16));
                        asm volatile("st.shared.b16 [%0], %1;" :: "r"(aL), "h"(*(uint16_t*)&bl16));
                    }
                }
            }
        }

        // flush pending half-0 h writes (GEMMs done reading A)
        #pragma unroll
        for (int mt = 0; mt < 2; ++mt) {
            #pragma unroll
            for (int nt = 0; nt < 8; ++nt) {
                int mrow = warp_m * 32 + mt * 16 + (lane >> 2) + ((lane & 1) ? 8 : 0);
                int r    = warp_n * 16 + nt * 2 + ((lane & 3) >> 1);
                if (sMask[mrow]) {
                    float hn = hpend[mt * 8 + nt];
                    uint32_t aH = a_addr(sbase + OFF_AHI, mrow, 128 + 2 * r);
                    uint32_t aL = a_addr(sbase + OFF_ALO, mrow, 128 + 2 * r);
                    __half bh16 = __float2half_rn(hn);
                    __half bl16 = __float2half_rn(hn - __half2float(bh16));
                    asm volatile("st.shared.b16 [%0], %1;" :: "r"(aH), "h"(*(uint16_t*)&bh16));
                    asm volatile("st.shared.b16 [%0], %1;" :: "r"(aL), "h"(*(uint16_t*)&bl16));
                }
            }
        }
        __syncthreads();

        // ---- output head ----
        {
            int s = t & 127, part = t >> 7;    // 4 parts x 32 r
            float o0 = 0, o1 = 0, o2 = 0, o3 = 0, o4 = 0;
            #pragma unroll
            for (int rr = 0; rr < 16; ++rr) {
                int r0 = part * 32 + rr * 2;
                uint32_t aH = a_addr(sbase + OFF_AHI, s, 128 + 2 * r0);
                uint32_t aL = a_addr(sbase + OFF_ALO, s, 128 + 2 * r0);
                uint32_t vh, vl;
                asm volatile("ld.shared.b32 %0, [%1];" : "=r"(vh) : "r"(aH));
                asm volatile("ld.shared.b32 %0, [%1];" : "=r"(vl) : "r"(aL));
                __half2 h2 = *reinterpret_cast<__half2*>(&vh);
                __half2 l2 = *reinterpret_cast<__half2*>(&vl);
                float ha = __half2float(h2.x) + __half2float(l2.x);
                float hb = __half2float(h2.y) + __half2float(l2.y);
                o0 = fmaf(ha, sWout[r0], fmaf(hb, sWout[r0 + 1], o0));
                o1 = fmaf(ha, sWout[128 + r0], fmaf(hb, sWout[128 + r0 + 1], o1));
                o2 = fmaf(ha, sWout[256 + r0], fmaf(hb, sWout[256 + r0 + 1], o2));
                o3 = fmaf(ha, sWout[384 + r0], fmaf(hb, sWout[384 + r0 + 1], o3));
                o4 = fmaf(ha, sWout[512 + r0], fmaf(hb, sWout[512 + r0 + 1], o4));
            }
            float* rp = &sRed[(s * 4 + part) * 5];
            rp[0] = o0; rp[1] = o1; rp[2] = o2; rp[3] = o3; rp[4] = o4;
        }
        __syncthreads();
        for (int idx = t; idx < 640; idx += NTHREADS) {
            int s2 = idx / 5, oo = idx % 5;
            float v = 0.f;
            if (sMask[s2]) {
                v = sRed[(s2 * 4 + 0) * 5 + oo] + sRed[(s2 * 4 + 1) * 5 + oo]
                  + sRed[(s2 * 4 + 2) * 5 + oo] + sRed[(s2 * 4 + 3) * 5 + oo] + sBout[oo];
            }
            out_y[((size_t)st * N_SEQ + n0 + s2) * OUT_DIM + oo] = v;
        }
        __syncthreads();
    }

    // ---- final h, c writeback ----
    {
        int m = t >> 2, rblk = (t & 3) * 32;
        float4* hp = (float4*)&out_h[(size_t)(n0 + m) * RDIM + rblk];
        float4* cp = (float4*)&out_c[(size_t)(n0 + m) * RDIM + rblk];
        #pragma unroll
        for (int jj = 0; jj < 8; ++jj) {
            int r0 = rblk + jj * 4;
            uint32_t vh0, vh1, vl0, vl1;
            uint32_t aH0 = a_addr(sbase + OFF_AHI, m, 128 + 2 * r0);
            uint32_t aH1 = a_addr(sbase + OFF_AHI, m, 128 + 2 * r0 + 4);
            uint32_t aL0 = a_addr(sbase + OFF_ALO, m, 128 + 2 * r0);
            uint32_t aL1 = a_addr(sbase + OFF_ALO, m, 128 + 2 * r0 + 4);
            asm volatile("ld.shared.b32 %0, [%1];" : "=r"(vh0) : "r"(aH0));
            asm volatile("ld.shared.b32 %0, [%1];" : "=r"(vh1) : "r"(aH1));
            asm volatile("ld.shared.b32 %0, [%1];" : "=r"(vl0) : "r"(aL0));
            asm volatile("ld.shared.b32 %0, [%1];" : "=r"(vl1) : "r"(aL1));
            __half2 h2a = *reinterpret_cast<__half2*>(&vh0);
            __half2 h2b = *reinterpret_cast<__half2*>(&vh1);
            __half2 l2a = *reinterpret_cast<__half2*>(&vl0);
            __half2 l2b = *reinterpret_cast<__half2*>(&vl1);
            float4 hv;
            hv.x = __half2float(h2a.x) + __half2float(l2a.x);
            hv.y = __half2float(h2a.y) + __half2float(l2a.y);
            hv.z = __half2float(h2b.x) + __half2float(l2b.x);
            hv.w = __half2float(h2b.y) + __half2float(l2b.y);
            hp[jj] = hv;
            cp[jj] = *(float4*)&sC[m * 128 + r0];
        }
    }
}

extern "C" void kernel_launch(void* const* d_in, const int* in_sizes, int n_in,
                              void* d_out, int out_size) {
    const float* input_data = (const float*)d_in[0];
    const float* h0         = (const float*)d_in[1];
    const float* c0         = (const float*)d_in[2];
    const int*   ped        = (const int*)  d_in[3];
    const float* W_emb      = (const float*)d_in[4];
    const float* b_emb      = (const float*)d_in[5];
    const float* W_ih       = (const float*)d_in[6];
    const float* W_hh       = (const float*)d_in[7];
    const float* b_ih       = (const float*)d_in[8];
    const float* b_hh       = (const float*)d_in[9];
    const float* W_out      = (const float*)d_in[10];
    const float* b_out      = (const float*)d_in[11];

    float* out   = (float*)d_out;
    float* out_y = out;                                      // [S][N][5]
    float* out_h = out + (size_t)S_LEN * N_SEQ * OUT_DIM;    // [N][128]
    float* out_c = out_h + (size_t)N_SEQ * RDIM;             // [N][128]

    prep_w<<<48, 128>>>(W_ih, W_hh);
    prep_bias<<<1, 512>>>(b_ih, b_hh);

    cudaFuncSetAttribute(lstm_mma, cudaFuncAttributeMaxDynamicSharedMemorySize, SMEM_TOTAL);
    lstm_mma<<<N_SEQ / TILE, NTHREADS, SMEM_TOTAL>>>(
        input_data, h0, c0, ped, W_emb, b_emb, W_out, b_out, out_y, out_h, out_c);
}

// round 7
// speedup vs baseline: 2.4188x; 1.2770x over previous
#include <cuda_runtime.h>
#include <cuda_fp16.h>
#include <cstdint>
#include <cstddef>

#define S_LEN   64
#define N_SEQ   65536
#define RDIM    128
#define OUT_DIM 5
#define TILE    128
#define NTHREADS 512
#define KDIM    192
#define NKC     12                      // k16 chunks per half
#define SLOTS_PER_STEP 24               // 2 halves x 12 kc
#define TOTAL_SLOTS (S_LEN * SLOTS_PER_STEP)   // 1536
#define SLOT_BYTES 8192                 // fp16: plane0 (k0-7) + plane1 (k8-15)
#define NBUF 4
#define APITCH 384                      // A row pitch bytes (192 k * 2B)

// ---- SMEM offsets (bytes) ----
#define OFF_AHI   0          // 128*384 = 49152  (MMA A operand, fp16 hi)
#define OFF_ALO   49152      // h-lo plane: STS/LDS only (head + writeback accuracy)
#define OFF_B     98304      // 4 x 8192 = 32768
#define OFF_C     131072     // 128*128 f32 = 65536
#define OFF_RED   196608     // 2560 f32 = 10240
#define OFF_BIAS  206848     // 512 f32
#define OFF_WOUT  208896     // 640 f32 -> 2560
#define OFF_X     211456     // 256 f32
#define OFF_MASK  212480     // 128 i32
#define OFF_WEMB  212992     // 128 f32
#define OFF_BEMB  213504     // 64 f32
#define OFF_BOUT  213760     // 8 f32
#define SMEM_TOTAL 213792

// ---- device scratch ----
__device__ __align__(16) unsigned char g_Bstream[SLOTS_PER_STEP * SLOT_BYTES]; // 192KB
__device__ float g_bias[512];

// ---- helpers ----
__device__ __forceinline__ uint32_t pack2h(float a, float b) {
    __half2 v = __floats2half2_rn(a, b);
    return *reinterpret_cast<uint32_t*>(&v);
}
__device__ __forceinline__ float h_hi(float a) { return __half2float(__float2half_rn(a)); }

__device__ __forceinline__ float sigf(float x) { return __fdividef(1.f, 1.f + __expf(-x)); }
__device__ __forceinline__ float tanh_(float x) { return fmaf(2.f, sigf(2.f * x), -1.f); }

__device__ __forceinline__ void cp_async16(uint32_t smem_dst, const void* gsrc) {
    asm volatile("cp.async.cg.shared.global [%0], [%1], 16;" :: "r"(smem_dst), "l"(gsrc));
}
__device__ __forceinline__ void cp_commit() { asm volatile("cp.async.commit_group;"); }
__device__ __forceinline__ void cp_wait_n(int n) {
    if (n >= 2)      asm volatile("cp.async.wait_group 2;");
    else if (n == 1) asm volatile("cp.async.wait_group 1;");
    else             asm volatile("cp.async.wait_group 0;");
}

__device__ __forceinline__ void ldsm4(uint32_t* r, uint32_t addr) {
    asm volatile("ldmatrix.sync.aligned.m8n8.x4.shared.b16 {%0,%1,%2,%3}, [%4];"
        : "=r"(r[0]), "=r"(r[1]), "=r"(r[2]), "=r"(r[3]) : "r"(addr));
}
__device__ __forceinline__ void mma16816h(float* c, const uint32_t* a, uint32_t b0, uint32_t b1) {
    asm volatile("mma.sync.aligned.m16n8k16.row.col.f32.f16.f16.f32 "
        "{%0,%1,%2,%3}, {%4,%5,%6,%7}, {%8,%9}, {%0,%1,%2,%3};"
        : "+f"(c[0]), "+f"(c[1]), "+f"(c[2]), "+f"(c[3])
        : "r"(a[0]), "r"(a[1]), "r"(a[2]), "r"(a[3]), "r"(b0), "r"(b1));
}

// A byte address with per-row XOR swizzle (conflict-free ldmatrix at pitch 384)
__device__ __forceinline__ uint32_t a_addr(uint32_t base, int m, int kb) {
    uint32_t kb16 = (uint32_t)kb & ~15u, off = (uint32_t)kb & 15u;
    return base + (uint32_t)m * APITCH + (kb16 ^ (((uint32_t)m & 7u) << 4)) + off;
}

// ---- prep: B stream, fp16. slot = nh*12+kc. Row j (0..255): r_local=j>>2, gate=j&3.
// Layout per slot: [0,4K) k0-7 | [4K,8K) k8-15
__global__ void prep_w(const float* __restrict__ Wih, const float* __restrict__ Whh) {
    int idx = blockIdx.x * 128 + threadIdx.x;      // 0..6143
    int slot = idx >> 8, j = idx & 255;
    int nh = slot / 12, kc = slot % 12;
    int gi = (j & 3) * 128 + nh * 64 + (j >> 2);
    uint32_t hi[8];
    #pragma unroll
    for (int p = 0; p < 8; ++p) {
        int k0 = kc * 16 + p * 2;
        float w0 = (k0     < 64) ? Wih[gi * 64 + k0]     : Whh[gi * 128 + k0 - 64];
        float w1 = (k0 + 1 < 64) ? Wih[gi * 64 + k0 + 1] : Whh[gi * 128 + k0 + 1 - 64];
        hi[p] = pack2h(w0, w1);
    }
    uint4* base = (uint4*)(g_Bstream + (size_t)slot * SLOT_BYTES + j * 16);
    base[0]         = make_uint4(hi[0], hi[1], hi[2], hi[3]);   // plane0
    base[4096 / 16] = make_uint4(hi[4], hi[5], hi[6], hi[7]);   // plane1
}
__global__ void prep_bias(const float* __restrict__ bih, const float* __restrict__ bhh) {
    int t = threadIdx.x; g_bias[t] = bih[t] + bhh[t];
}

// ---- main kernel ----
__global__ void __launch_bounds__(NTHREADS, 1)
lstm_mma(const float* __restrict__ input_data,
         const float* __restrict__ h0,
         const float* __restrict__ c0,
         const int*   __restrict__ ped_mask,
         const float* __restrict__ W_emb,
         const float* __restrict__ b_emb,
         const float* __restrict__ W_out,
         const float* __restrict__ b_out,
         float* __restrict__ out_y,
         float* __restrict__ out_h,
         float* __restrict__ out_c)
{
    extern __shared__ unsigned char smem[];
    const uint32_t sbase = (uint32_t)__cvta_generic_to_shared(smem);
    const int t = threadIdx.x, lane = t & 31, wid = t >> 5;
    const int warp_m = wid >> 2, warp_n = wid & 3;
    const int n0 = blockIdx.x * TILE;

    float* sC    = (float*)(smem + OFF_C);
    float* sRed  = (float*)(smem + OFF_RED);
    float* sBias = (float*)(smem + OFF_BIAS);
    float* sWout = (float*)(smem + OFF_WOUT);
    float* sX    = (float*)(smem + OFF_X);
    int*   sMask = (int*)  (smem + OFF_MASK);
    float* sWemb = (float*)(smem + OFF_WEMB);
    float* sBemb = (float*)(smem + OFF_BEMB);
    float* sBout = (float*)(smem + OFF_BOUT);

    // stage constants
    sBias[t] = g_bias[t];
    for (int i = t; i < 640; i += NTHREADS) sWout[i] = W_out[i];
    if (t < 128) sWemb[t] = W_emb[t];
    if (t < 64)  sBemb[t] = b_emb[t];
    if (t < 5)   sBout[t] = b_out[t];

    // init h -> A (fp16 hi; lo plane for accuracy of head/writeback), c -> sC
    {
        int m = t >> 2, rblk = (t & 3) * 32;
        const float4* hp = (const float4*)&h0[(size_t)(n0 + m) * RDIM + rblk];
        const float4* cp = (const float4*)&c0[(size_t)(n0 + m) * RDIM + rblk];
        #pragma unroll
        for (int jj = 0; jj < 8; ++jj) {
            float4 hv = hp[jj], cv = cp[jj];
            *(float4*)&sC[m * 128 + rblk + jj * 4] = cv;
            int r0 = rblk + jj * 4;
            uint32_t aH0 = a_addr(sbase + OFF_AHI, m, 128 + 2 * r0);
            uint32_t aH1 = a_addr(sbase + OFF_AHI, m, 128 + 2 * r0 + 4);
            uint32_t aL0 = a_addr(sbase + OFF_ALO, m, 128 + 2 * r0);
            uint32_t aL1 = a_addr(sbase + OFF_ALO, m, 128 + 2 * r0 + 4);
            uint32_t vh0 = pack2h(hv.x, hv.y), vh1 = pack2h(hv.z, hv.w);
            uint32_t vl0 = pack2h(hv.x - h_hi(hv.x), hv.y - h_hi(hv.y));
            uint32_t vl1 = pack2h(hv.z - h_hi(hv.z), hv.w - h_hi(hv.w));
            asm volatile("st.shared.b32 [%0], %1;" :: "r"(aH0), "r"(vh0));
            asm volatile("st.shared.b32 [%0], %1;" :: "r"(aH1), "r"(vh1));
            asm volatile("st.shared.b32 [%0], %1;" :: "r"(aL0), "r"(vl0));
            asm volatile("st.shared.b32 [%0], %1;" :: "r"(aL1), "r"(vl1));
        }
    }

    // prologue: slots 0,1,2 in flight (1 cp16 per thread per slot: 8KB)
    #pragma unroll
    for (int s = 0; s < 3; ++s) {
        cp_async16(sbase + OFF_B + (uint32_t)s * SLOT_BYTES + t * 16u,
                   g_Bstream + (size_t)s * SLOT_BYTES + t * 16);
        cp_commit();
    }
    __syncthreads();

    float hpend[16];

    #pragma unroll 1
    for (int st = 0; st < S_LEN; ++st) {
        // stage x, mask
        if (t < 64) {
            ((float4*)sX)[t] = ((const float4*)(input_data + ((size_t)st * N_SEQ + n0) * 2))[t];
        } else if (t < 96) {
            ((int4*)sMask)[t - 64] = ((const int4*)(ped_mask + (size_t)st * N_SEQ + n0))[t - 64];
        }
        __syncthreads();

        // embedding -> A cols 0..63 (fp16 hi only — lo never read by MMA or head here)
        {
            int kp = lane, sg = wid;
            float w00 = sWemb[kp * 4], w01 = sWemb[kp * 4 + 1];
            float w10 = sWemb[kp * 4 + 2], w11 = sWemb[kp * 4 + 3];
            float bb0 = sBemb[kp * 2], bb1 = sBemb[kp * 2 + 1];
            #pragma unroll
            for (int q = 0; q < 8; ++q) {
                int s2 = sg * 8 + q;
                float x0 = sX[s2 * 2], x1 = sX[s2 * 2 + 1];
                float e0 = fmaxf(fmaf(w00, x0, fmaf(w01, x1, bb0)), 0.f);
                float e1 = fmaxf(fmaf(w10, x0, fmaf(w11, x1, bb1)), 0.f);
                uint32_t aH = a_addr(sbase + OFF_AHI, s2, kp * 4);
                asm volatile("st.shared.b32 [%0], %1;" :: "r"(aH), "r"(pack2h(e0, e1)));
            }
        }

        // ---- two halves: gates for r in [nh*64, nh*64+64) ----
        #pragma unroll 1
        for (int nh = 0; nh < 2; ++nh) {
            float acc[2][8][4];
            #pragma unroll
            for (int a = 0; a < 2; ++a)
                #pragma unroll
                for (int b = 0; b < 8; ++b)
                    #pragma unroll
                    for (int d = 0; d < 4; ++d) acc[a][b][d] = 0.f;

            #pragma unroll 1
            for (int kc = 0; kc < NKC; ++kc) {
                int g = st * SLOTS_PER_STEP + nh * NKC + kc;
                int rem = TOTAL_SLOTS - 1 - g;
                cp_wait_n(rem < 2 ? rem : 2);
                __syncthreads();
                int q = g + 3;
                if (q < TOTAL_SLOTS) {
                    cp_async16(sbase + OFF_B + (uint32_t)(q % NBUF) * SLOT_BYTES + t * 16u,
                               g_Bstream + (size_t)(q % SLOTS_PER_STEP) * SLOT_BYTES + t * 16);
                    cp_commit();
                }
                uint32_t sbuf = sbase + OFF_B + (uint32_t)(g % NBUF) * SLOT_BYTES;

                // A fragments (hi only) for 2 m-tiles
                uint32_t ah[2][4];
                int arow = warp_m * 32 + (lane & 15);
                int akb  = kc * 32 + ((lane >> 4) << 4);
                ldsm4(ah[0], a_addr(sbase + OFF_AHI, arow, akb));
                ldsm4(ah[1], a_addr(sbase + OFF_AHI, arow + 16, akb));
                // B: 4 groups of 2 n8-tiles
                int msel = lane >> 3, r8 = lane & 7;
                uint32_t brow_off = (uint32_t)(warp_n * 64 + ((msel >> 1) << 3) + r8) * 16u
                                  + (uint32_t)(msel & 1) * 4096u;
                #pragma unroll
                for (int p = 0; p < 4; ++p) {
                    uint32_t bh[4];
                    ldsm4(bh, sbuf + brow_off + (uint32_t)p * 256u);
                    #pragma unroll
                    for (int mt = 0; mt < 2; ++mt) {
                        mma16816h(acc[mt][2 * p],     ah[mt], bh[0], bh[1]);
                        mma16816h(acc[mt][2 * p + 1], ah[mt], bh[2], bh[3]);
                    }
                }
            }

            // ---- cell for this half ----
            const int odd = lane & 1;
            #pragma unroll
            for (int mt = 0; mt < 2; ++mt) {
                #pragma unroll
                for (int nt = 0; nt < 8; ++nt) {
                    float c0 = acc[mt][nt][0], c1 = acc[mt][nt][1];
                    float c2 = acc[mt][nt][2], c3 = acc[mt][nt][3];
                    float e0 = __shfl_xor_sync(0xffffffffu, c0, 1);
                    float e1 = __shfl_xor_sync(0xffffffffu, c1, 1);
                    float e2 = __shfl_xor_sync(0xffffffffu, c2, 1);
                    float e3 = __shfl_xor_sync(0xffffffffu, c3, 1);
                    int mrow = warp_m * 32 + mt * 16 + (lane >> 2) + (odd ? 8 : 0);
                    int rl   = warp_n * 16 + nt * 2 + ((lane & 3) >> 1);
                    int r    = nh * 64 + rl;
                    float zi = odd ? e2 : c0;
                    float zf = odd ? e3 : c1;
                    float zg = odd ? c2 : e0;
                    float zo = odd ? c3 : e1;
                    zi += sBias[r]; zf += sBias[128 + r];
                    zg += sBias[256 + r]; zo += sBias[384 + r];
                    float co = sC[mrow * 128 + r];
                    float cn = fmaf(sigf(zf), co, sigf(zi) * tanh_(zg));
                    float hn = sigf(zo) * tanh_(cn);
                    int msk = sMask[mrow];
                    if (msk) sC[mrow * 128 + r] = cn;
                    if (nh == 0) {
                        hpend[mt * 8 + nt] = hn;
                    } else if (msk) {
                        uint32_t aH = a_addr(sbase + OFF_AHI, mrow, 128 + 2 * r);
                        uint32_t aL = a_addr(sbase + OFF_ALO, mrow, 128 + 2 * r);
                        __half bh16 = __float2half_rn(hn);
                        __half bl16 = __float2half_rn(hn - __half2float(bh16));
                        asm volatile("st.shared.b16 [%0], %1;" :: "r"(aH), "h"(*(uint16_t*)&bh16));
                        asm volatile("st.shared.b16 [%0], %1;" :: "r"(aL), "h"(*(uint16_t*)&bl16));
                    }
                }
            }
        }

        // flush pending half-0 h writes (GEMMs done reading A)
        #pragma unroll
        for (int mt = 0; mt < 2; ++mt) {
            #pragma unroll
            for (int nt = 0; nt < 8; ++nt) {
                int mrow = warp_m * 32 + mt * 16 + (lane >> 2) + ((lane & 1) ? 8 : 0);
                int r    = warp_n * 16 + nt * 2 + ((lane & 3) >> 1);
                if (sMask[mrow]) {
                    float hn = hpend[mt * 8 + nt];
                    uint32_t aH = a_addr(sbase + OFF_AHI, mrow, 128 + 2 * r);
                    uint32_t aL = a_addr(sbase + OFF_ALO, mrow, 128 + 2 * r);
                    __half bh16 = __float2half_rn(hn);
                    __half bl16 = __float2half_rn(hn - __half2float(bh16));
                    asm volatile("st.shared.b16 [%0], %1;" :: "r"(aH), "h"(*(uint16_t*)&bh16));
                    asm volatile("st.shared.b16 [%0], %1;" :: "r"(aL), "h"(*(uint16_t*)&bl16));
                }
            }
        }
        __syncthreads();

        // ---- output head (reads h hi+lo => fp32-class h) ----
        {
            int s = t & 127, part = t >> 7;    // 4 parts x 32 r
            float o0 = 0, o1 = 0, o2 = 0, o3 = 0, o4 = 0;
            #pragma unroll
            for (int rr = 0; rr < 16; ++rr) {
                int r0 = part * 32 + rr * 2;
                uint32_t aH = a_addr(sbase + OFF_AHI, s, 128 + 2 * r0);
                uint32_t aL = a_addr(sbase + OFF_ALO, s, 128 + 2 * r0);
                uint32_t vh, vl;
                asm volatile("ld.shared.b32 %0, [%1];" : "=r"(vh) : "r"(aH));
                asm volatile("ld.shared.b32 %0, [%1];" : "=r"(vl) : "r"(aL));
                __half2 h2 = *reinterpret_cast<__half2*>(&vh);
                __half2 l2 = *reinterpret_cast<__half2*>(&vl);
                float ha = __half2float(h2.x) + __half2float(l2.x);
                float hb = __half2float(h2.y) + __half2float(l2.y);
                o0 = fmaf(ha, sWout[r0], fmaf(hb, sWout[r0 + 1], o0));
                o1 = fmaf(ha, sWout[128 + r0], fmaf(hb, sWout[128 + r0 + 1], o1));
                o2 = fmaf(ha, sWout[256 + r0], fmaf(hb, sWout[256 + r0 + 1], o2));
                o3 = fmaf(ha, sWout[384 + r0], fmaf(hb, sWout[384 + r0 + 1], o3));
                o4 = fmaf(ha, sWout[512 + r0], fmaf(hb, sWout[512 + r0 + 1], o4));
            }
            float* rp = &sRed[(s * 4 + part) * 5];
            rp[0] = o0; rp[1] = o1; rp[2] = o2; rp[3] = o3; rp[4] = o4;
        }
        __syncthreads();
        for (int idx = t; idx < 640; idx += NTHREADS) {
            int s2 = idx / 5, oo = idx % 5;
            float v = 0.f;
            if (sMask[s2]) {
                v = sRed[(s2 * 4 + 0) * 5 + oo] + sRed[(s2 * 4 + 1) * 5 + oo]
                  + sRed[(s2 * 4 + 2) * 5 + oo] + sRed[(s2 * 4 + 3) * 5 + oo] + sBout[oo];
            }
            out_y[((size_t)st * N_SEQ + n0 + s2) * OUT_DIM + oo] = v;
        }
        __syncthreads();
    }

    // ---- final h, c writeback (h = hi + lo) ----
    {
        int m = t >> 2, rblk = (t & 3) * 32;
        float4* hp = (float4*)&out_h[(size_t)(n0 + m) * RDIM + rblk];
        float4* cp = (float4*)&out_c[(size_t)(n0 + m) * RDIM + rblk];
        #pragma unroll
        for (int jj = 0; jj < 8; ++jj) {
            int r0 = rblk + jj * 4;
            uint32_t vh0, vh1, vl0, vl1;
            uint32_t aH0 = a_addr(sbase + OFF_AHI, m, 128 + 2 * r0);
            uint32_t aH1 = a_addr(sbase + OFF_AHI, m, 128 + 2 * r0 + 4);
            uint32_t aL0 = a_addr(sbase + OFF_ALO, m, 128 + 2 * r0);
            uint32_t aL1 = a_addr(sbase + OFF_ALO, m, 128 + 2 * r0 + 4);
            asm volatile("ld.shared.b32 %0, [%1];" : "=r"(vh0) : "r"(aH0));
            asm volatile("ld.shared.b32 %0, [%1];" : "=r"(vh1) : "r"(aH1));
            asm volatile("ld.shared.b32 %0, [%1];" : "=r"(vl0) : "r"(aL0));
            asm volatile("ld.shared.b32 %0, [%1];" : "=r"(vl1) : "r"(aL1));
            __half2 h2a = *reinterpret_cast<__half2*>(&vh0);
            __half2 h2b = *reinterpret_cast<__half2*>(&vh1);
            __half2 l2a = *reinterpret_cast<__half2*>(&vl0);
            __half2 l2b = *reinterpret_cast<__half2*>(&vl1);
            float4 hv;
            hv.x = __half2float(h2a.x) + __half2float(l2a.x);
            hv.y = __half2float(h2a.y) + __half2float(l2a.y);
            hv.z = __half2float(h2b.x) + __half2float(l2b.x);
            hv.w = __half2float(h2b.y) + __half2float(l2b.y);
            hp[jj] = hv;
            cp[jj] = *(float4*)&sC[m * 128 + r0];
        }
    }
}

extern "C" void kernel_launch(void* const* d_in, const int* in_sizes, int n_in,
                              void* d_out, int out_size) {
    const float* input_data = (const float*)d_in[0];
    const float* h0         = (const float*)d_in[1];
    const float* c0         = (const float*)d_in[2];
    const int*   ped        = (const int*)  d_in[3];
    const float* W_emb      = (const float*)d_in[4];
    const float* b_emb      = (const float*)d_in[5];
    const float* W_ih       = (const float*)d_in[6];
    const float* W_hh       = (const float*)d_in[7];
    const float* b_ih       = (const float*)d_in[8];
    const float* b_hh       = (const float*)d_in[9];
    const float* W_out      = (const float*)d_in[10];
    const float* b_out      = (const float*)d_in[11];

    float* out   = (float*)d_out;
    float* out_y = out;                                      // [S][N][5]
    float* out_h = out + (size_t)S_LEN * N_SEQ * OUT_DIM;    // [N][128]
    float* out_c = out_h + (size_t)N_SEQ * RDIM;             // [N][128]

    prep_w<<<48, 128>>>(W_ih, W_hh);
    prep_bias<<<1, 512>>>(b_ih, b_hh);

    cudaFuncSetAttribute(lstm_mma, cudaFuncAttributeMaxDynamicSharedMemorySize, SMEM_TOTAL);
    lstm_mma<<<N_SEQ / TILE, NTHREADS, SMEM_TOTAL>>>(
        input_data, h0, c0, ped, W_emb, b_emb, W_out, b_out, out_y, out_h, out_c);
}

// round 8
// speedup vs baseline: 3.0245x; 1.2504x over previous
#include <cuda_runtime.h>
#include <cuda_fp16.h>
#include <cstdint>
#include <cstddef>

#define S_LEN   64
#define N_SEQ   65536
#define RDIM    128
#define OUT_DIM 5
#define TILE    64
#define NTHREADS 256
#define KDIM    192
#define NKC     12                      // k16 chunks per half
#define SLOTS_PER_STEP 24               // 2 halves x 12 kc
#define TOTAL_SLOTS (S_LEN * SLOTS_PER_STEP)   // 1536
#define SLOT_BYTES 8192                 // fp16: plane0 (k0-7) + plane1 (k8-15)
#define NBUF 4
#define APITCH 384                      // A row pitch bytes (192 k * 2B)

// ---- SMEM offsets (bytes), total 101408 -> 2 CTAs/SM ----
#define OFF_AHI   0          // 64*384 = 24576 (fp16 hi: e | h)
#define OFF_B     24576      // 4 x 8192 = 32768
#define OFF_C     57344      // 64*128 f32 = 32768
#define OFF_RED   90112      // 64*4*5 f32 = 5120
#define OFF_BIAS  95232      // 512 f32
#define OFF_WOUT  97280      // 640 f32
#define OFF_X     99840      // 128 f32
#define OFF_MASK  100352     // 64 i32
#define OFF_WEMB  100608     // 128 f32
#define OFF_BEMB  101120     // 64 f32
#define OFF_BOUT  101376     // 8 f32
#define SMEM_TOTAL 101408

// ---- device scratch ----
__device__ __align__(16) unsigned char g_Bstream[SLOTS_PER_STEP * SLOT_BYTES]; // 192KB
__device__ float g_bias[512];

// ---- helpers ----
__device__ __forceinline__ uint32_t pack2h(float a, float b) {
    __half2 v = __floats2half2_rn(a, b);
    return *reinterpret_cast<uint32_t*>(&v);
}
__device__ __forceinline__ float sigf(float x) { return __fdividef(1.f, 1.f + __expf(-x)); }
__device__ __forceinline__ float tanh_(float x) { return fmaf(2.f, sigf(2.f * x), -1.f); }

__device__ __forceinline__ void cp_async16(uint32_t smem_dst, const void* gsrc) {
    asm volatile("cp.async.cg.shared.global [%0], [%1], 16;" :: "r"(smem_dst), "l"(gsrc));
}
__device__ __forceinline__ void cp_commit() { asm volatile("cp.async.commit_group;"); }
__device__ __forceinline__ void cp_wait_n(int n) {
    if (n >= 2)      asm volatile("cp.async.wait_group 2;");
    else if (n == 1) asm volatile("cp.async.wait_group 1;");
    else             asm volatile("cp.async.wait_group 0;");
}

__device__ __forceinline__ void ldsm4(uint32_t* r, uint32_t addr) {
    asm volatile("ldmatrix.sync.aligned.m8n8.x4.shared.b16 {%0,%1,%2,%3}, [%4];"
        : "=r"(r[0]), "=r"(r[1]), "=r"(r[2]), "=r"(r[3]) : "r"(addr));
}
__device__ __forceinline__ void mma16816h(float* c, const uint32_t* a, uint32_t b0, uint32_t b1) {
    asm volatile("mma.sync.aligned.m16n8k16.row.col.f32.f16.f16.f32 "
        "{%0,%1,%2,%3}, {%4,%5,%6,%7}, {%8,%9}, {%0,%1,%2,%3};"
        : "+f"(c[0]), "+f"(c[1]), "+f"(c[2]), "+f"(c[3])
        : "r"(a[0]), "r"(a[1]), "r"(a[2]), "r"(a[3]), "r"(b0), "r"(b1));
}

// A byte address with per-row XOR swizzle (conflict-free ldmatrix at pitch 384)
__device__ __forceinline__ uint32_t a_addr(uint32_t base, int m, int kb) {
    uint32_t kb16 = (uint32_t)kb & ~15u, off = (uint32_t)kb & 15u;
    return base + (uint32_t)m * APITCH + (kb16 ^ (((uint32_t)m & 7u) << 4)) + off;
}

// ---- prep: B stream, fp16. slot = nh*12+kc. Row j (0..255): r_local=j>>2, gate=j&3.
// Layout per slot: [0,4K) k0-7 | [4K,8K) k8-15
__global__ void prep_w(const float* __restrict__ Wih, const float* __restrict__ Whh) {
    int idx = blockIdx.x * 128 + threadIdx.x;      // 0..6143
    int slot = idx >> 8, j = idx & 255;
    int nh = slot / 12, kc = slot % 12;
    int gi = (j & 3) * 128 + nh * 64 + (j >> 2);
    uint32_t hi[8];
    #pragma unroll
    for (int p = 0; p < 8; ++p) {
        int k0 = kc * 16 + p * 2;
        float w0 = (k0     < 64) ? Wih[gi * 64 + k0]     : Whh[gi * 128 + k0 - 64];
        float w1 = (k0 + 1 < 64) ? Wih[gi * 64 + k0 + 1] : Whh[gi * 128 + k0 + 1 - 64];
        hi[p] = pack2h(w0, w1);
    }
    uint4* base = (uint4*)(g_Bstream + (size_t)slot * SLOT_BYTES + j * 16);
    base[0]         = make_uint4(hi[0], hi[1], hi[2], hi[3]);   // plane0
    base[4096 / 16] = make_uint4(hi[4], hi[5], hi[6], hi[7]);   // plane1
}
__global__ void prep_bias(const float* __restrict__ bih, const float* __restrict__ bhh) {
    int t = threadIdx.x; g_bias[t] = bih[t] + bhh[t];
}

// ---- main kernel: TILE=64, 256 threads, 2 CTAs/SM for tensor/serial overlap ----
__global__ void __launch_bounds__(NTHREADS, 2)
lstm_mma(const float* __restrict__ input_data,
         const float* __restrict__ h0,
         const float* __restrict__ c0,
         const int*   __restrict__ ped_mask,
         const float* __restrict__ W_emb,
         const float* __restrict__ b_emb,
         const float* __restrict__ W_out,
         const float* __restrict__ b_out,
         float* __restrict__ out_y,
         float* __restrict__ out_h,
         float* __restrict__ out_c)
{
    extern __shared__ unsigned char smem[];
    const uint32_t sbase = (uint32_t)__cvta_generic_to_shared(smem);
    const int t = threadIdx.x, lane = t & 31, wid = t >> 5;     // 8 warps
    const int warp_m = wid >> 2, warp_n = wid & 3;              // 2 x 4
    const int n0 = blockIdx.x * TILE;

    float* sC    = (float*)(smem + OFF_C);
    float* sRed  = (float*)(smem + OFF_RED);
    float* sBias = (float*)(smem + OFF_BIAS);
    float* sWout = (float*)(smem + OFF_WOUT);
    float* sX    = (float*)(smem + OFF_X);
    int*   sMask = (int*)  (smem + OFF_MASK);
    float* sWemb = (float*)(smem + OFF_WEMB);
    float* sBemb = (float*)(smem + OFF_BEMB);
    float* sBout = (float*)(smem + OFF_BOUT);

    // stage constants
    for (int i = t; i < 512; i += NTHREADS) sBias[i] = g_bias[i];
    for (int i = t; i < 640; i += NTHREADS) sWout[i] = W_out[i];
    if (t < 128) sWemb[t] = W_emb[t];
    else if (t < 192) sBemb[t - 128] = b_emb[t - 128];
    else if (t < 197) sBout[t - 192] = b_out[t - 192];

    // init h -> A (fp16 hi), c -> sC
    {
        int m = t >> 2, rblk = (t & 3) * 32;
        const float4* hp = (const float4*)&h0[(size_t)(n0 + m) * RDIM + rblk];
        const float4* cp = (const float4*)&c0[(size_t)(n0 + m) * RDIM + rblk];
        #pragma unroll
        for (int jj = 0; jj < 8; ++jj) {
            float4 hv = hp[jj], cv = cp[jj];
            *(float4*)&sC[m * 128 + rblk + jj * 4] = cv;
            int r0 = rblk + jj * 4;
            uint32_t aH0 = a_addr(sbase + OFF_AHI, m, 128 + 2 * r0);
            uint32_t aH1 = a_addr(sbase + OFF_AHI, m, 128 + 2 * r0 + 4);
            asm volatile("st.shared.b32 [%0], %1;" :: "r"(aH0), "r"(pack2h(hv.x, hv.y)));
            asm volatile("st.shared.b32 [%0], %1;" :: "r"(aH1), "r"(pack2h(hv.z, hv.w)));
        }
    }

    // prologue: slots 0,1,2 in flight (2 cp16 per thread per slot: 8KB)
    #pragma unroll
    for (int s = 0; s < 3; ++s) {
        uint32_t d = sbase + OFF_B + (uint32_t)s * SLOT_BYTES;
        const unsigned char* g = g_Bstream + (size_t)s * SLOT_BYTES;
        cp_async16(d + t * 16u, g + t * 16);
        cp_async16(d + (t + 256) * 16u, g + (size_t)(t + 256) * 16);
        cp_commit();
    }
    __syncthreads();

    float hpend[16];

    #pragma unroll 1
    for (int st = 0; st < S_LEN; ++st) {
        // stage x, mask
        if (t < 32) {
            ((float4*)sX)[t] = ((const float4*)(input_data + ((size_t)st * N_SEQ + n0) * 2))[t];
        } else if (t < 48) {
            ((int4*)sMask)[t - 32] = ((const int4*)(ped_mask + (size_t)st * N_SEQ + n0))[t - 32];
        }
        __syncthreads();

        // embedding -> A cols 0..63 (fp16 hi)
        {
            int kp = lane, sg = wid;          // 8 warps x 8 seqs = 64
            float w00 = sWemb[kp * 4], w01 = sWemb[kp * 4 + 1];
            float w10 = sWemb[kp * 4 + 2], w11 = sWemb[kp * 4 + 3];
            float bb0 = sBemb[kp * 2], bb1 = sBemb[kp * 2 + 1];
            #pragma unroll
            for (int q = 0; q < 8; ++q) {
                int s2 = sg * 8 + q;
                float x0 = sX[s2 * 2], x1 = sX[s2 * 2 + 1];
                float e0 = fmaxf(fmaf(w00, x0, fmaf(w01, x1, bb0)), 0.f);
                float e1 = fmaxf(fmaf(w10, x0, fmaf(w11, x1, bb1)), 0.f);
                uint32_t aH = a_addr(sbase + OFF_AHI, s2, kp * 4);
                asm volatile("st.shared.b32 [%0], %1;" :: "r"(aH), "r"(pack2h(e0, e1)));
            }
        }

        // ---- two halves: gates for r in [nh*64, nh*64+64) ----
        #pragma unroll 1
        for (int nh = 0; nh < 2; ++nh) {
            float acc[2][8][4];
            #pragma unroll
            for (int a = 0; a < 2; ++a)
                #pragma unroll
                for (int b = 0; b < 8; ++b)
                    #pragma unroll
                    for (int d = 0; d < 4; ++d) acc[a][b][d] = 0.f;

            #pragma unroll 1
            for (int kc = 0; kc < NKC; ++kc) {
                int g = st * SLOTS_PER_STEP + nh * NKC + kc;
                int rem = TOTAL_SLOTS - 1 - g;
                cp_wait_n(rem < 2 ? rem : 2);
                __syncthreads();
                int q = g + 3;
                if (q < TOTAL_SLOTS) {
                    uint32_t d = sbase + OFF_B + (uint32_t)(q % NBUF) * SLOT_BYTES;
                    const unsigned char* gp = g_Bstream + (size_t)(q % SLOTS_PER_STEP) * SLOT_BYTES;
                    cp_async16(d + t * 16u, gp + t * 16);
                    cp_async16(d + (t + 256) * 16u, gp + (size_t)(t + 256) * 16);
                    cp_commit();
                }
                uint32_t sbuf = sbase + OFF_B + (uint32_t)(g % NBUF) * SLOT_BYTES;

                // A fragments (hi only) for 2 m-tiles
                uint32_t ah[2][4];
                int arow = warp_m * 32 + (lane & 15);
                int akb  = kc * 32 + ((lane >> 4) << 4);
                ldsm4(ah[0], a_addr(sbase + OFF_AHI, arow, akb));
                ldsm4(ah[1], a_addr(sbase + OFF_AHI, arow + 16, akb));
                // B: 4 groups of 2 n8-tiles
                int msel = lane >> 3, r8 = lane & 7;
                uint32_t brow_off = (uint32_t)(warp_n * 64 + ((msel >> 1) << 3) + r8) * 16u
                                  + (uint32_t)(msel & 1) * 4096u;
                #pragma unroll
                for (int p = 0; p < 4; ++p) {
                    uint32_t bh[4];
                    ldsm4(bh, sbuf + brow_off + (uint32_t)p * 256u);
                    #pragma unroll
                    for (int mt = 0; mt < 2; ++mt) {
                        mma16816h(acc[mt][2 * p],     ah[mt], bh[0], bh[1]);
                        mma16816h(acc[mt][2 * p + 1], ah[mt], bh[2], bh[3]);
                    }
                }
            }

            // ---- cell for this half ----
            const int odd = lane & 1;
            #pragma unroll
            for (int mt = 0; mt < 2; ++mt) {
                #pragma unroll
                for (int nt = 0; nt < 8; ++nt) {
                    float c0 = acc[mt][nt][0], c1 = acc[mt][nt][1];
                    float c2 = acc[mt][nt][2], c3 = acc[mt][nt][3];
                    float e0 = __shfl_xor_sync(0xffffffffu, c0, 1);
                    float e1 = __shfl_xor_sync(0xffffffffu, c1, 1);
                    float e2 = __shfl_xor_sync(0xffffffffu, c2, 1);
                    float e3 = __shfl_xor_sync(0xffffffffu, c3, 1);
                    int mrow = warp_m * 32 + mt * 16 + (lane >> 2) + (odd ? 8 : 0);
                    int rl   = warp_n * 16 + nt * 2 + ((lane & 3) >> 1);
                    int r    = nh * 64 + rl;
                    float zi = odd ? e2 : c0;
                    float zf = odd ? e3 : c1;
                    float zg = odd ? c2 : e0;
                    float zo = odd ? c3 : e1;
                    zi += sBias[r]; zf += sBias[128 + r];
                    zg += sBias[256 + r]; zo += sBias[384 + r];
                    float co = sC[mrow * 128 + r];
                    float cn = fmaf(sigf(zf), co, sigf(zi) * tanh_(zg));
                    float hn = sigf(zo) * tanh_(cn);
                    int msk = sMask[mrow];
                    if (msk) sC[mrow * 128 + r] = cn;
                    if (nh == 0) {
                        hpend[mt * 8 + nt] = hn;
                    } else if (msk) {
                        uint32_t aH = a_addr(sbase + OFF_AHI, mrow, 128 + 2 * r);
                        __half bh16 = __float2half_rn(hn);
                        asm volatile("st.shared.b16 [%0], %1;" :: "r"(aH), "h"(*(uint16_t*)&bh16));
                    }
                }
            }
        }

        // flush pending half-0 h writes (GEMMs done reading A)
        #pragma unroll
        for (int mt = 0; mt < 2; ++mt) {
            #pragma unroll
            for (int nt = 0; nt < 8; ++nt) {
                int mrow = warp_m * 32 + mt * 16 + (lane >> 2) + ((lane & 1) ? 8 : 0);
                int r    = warp_n * 16 + nt * 2 + ((lane & 3) >> 1);
                if (sMask[mrow]) {
                    uint32_t aH = a_addr(sbase + OFF_AHI, mrow, 128 + 2 * r);
                    __half bh16 = __float2half_rn(hpend[mt * 8 + nt]);
                    asm volatile("st.shared.b16 [%0], %1;" :: "r"(aH), "h"(*(uint16_t*)&bh16));
                }
            }
        }
        __syncthreads();

        // ---- output head (h from fp16-hi plane) ----
        {
            int s = t & 63, part = t >> 6;    // 4 parts x 32 r
            float o0 = 0, o1 = 0, o2 = 0, o3 = 0, o4 = 0;
            #pragma unroll
            for (int rr = 0; rr < 16; ++rr) {
                int r0 = part * 32 + rr * 2;
                uint32_t aH = a_addr(sbase + OFF_AHI, s, 128 + 2 * r0);
                uint32_t vh;
                asm volatile("ld.shared.b32 %0, [%1];" : "=r"(vh) : "r"(aH));
                __half2 h2 = *reinterpret_cast<__half2*>(&vh);
                float ha = __half2float(h2.x);
                float hb = __half2float(h2.y);
                o0 = fmaf(ha, sWout[r0], fmaf(hb, sWout[r0 + 1], o0));
                o1 = fmaf(ha, sWout[128 + r0], fmaf(hb, sWout[128 + r0 + 1], o1));
                o2 = fmaf(ha, sWout[256 + r0], fmaf(hb, sWout[256 + r0 + 1], o2));
                o3 = fmaf(ha, sWout[384 + r0], fmaf(hb, sWout[384 + r0 + 1], o3));
                o4 = fmaf(ha, sWout[512 + r0], fmaf(hb, sWout[512 + r0 + 1], o4));
            }
            float* rp = &sRed[(s * 4 + part) * 5];
            rp[0] = o0; rp[1] = o1; rp[2] = o2; rp[3] = o3; rp[4] = o4;
        }
        __syncthreads();
        for (int idx = t; idx < 320; idx += NTHREADS) {
            int s2 = idx / 5, oo = idx % 5;
            float v = 0.f;
            if (sMask[s2]) {
                v = sRed[(s2 * 4 + 0) * 5 + oo] + sRed[(s2 * 4 + 1) * 5 + oo]
                  + sRed[(s2 * 4 + 2) * 5 + oo] + sRed[(s2 * 4 + 3) * 5 + oo] + sBout[oo];
            }
            out_y[((size_t)st * N_SEQ + n0 + s2) * OUT_DIM + oo] = v;
        }
        __syncthreads();
    }

    // ---- final h, c writeback ----
    {
        int m = t >> 2, rblk = (t & 3) * 32;
        float4* hp = (float4*)&out_h[(size_t)(n0 + m) * RDIM + rblk];
        float4* cp = (float4*)&out_c[(size_t)(n0 + m) * RDIM + rblk];
        #pragma unroll
        for (int jj = 0; jj < 8; ++jj) {
            int r0 = rblk + jj * 4;
            uint32_t vh0, vh1;
            uint32_t aH0 = a_addr(sbase + OFF_AHI, m, 128 + 2 * r0);
            uint32_t aH1 = a_addr(sbase + OFF_AHI, m, 128 + 2 * r0 + 4);
            asm volatile("ld.shared.b32 %0, [%1];" : "=r"(vh0) : "r"(aH0));
            asm volatile("ld.shared.b32 %0, [%1];" : "=r"(vh1) : "r"(aH1));
            __half2 h2a = *reinterpret_cast<__half2*>(&vh0);
            __half2 h2b = *reinterpret_cast<__half2*>(&vh1);
            float4 hv;
            hv.x = __half2float(h2a.x);
            hv.y = __half2float(h2a.y);
            hv.z = __half2float(h2b.x);
            hv.w = __half2float(h2b.y);
            hp[jj] = hv;
            cp[jj] = *(float4*)&sC[m * 128 + r0];
        }
    }
}

extern "C" void kernel_launch(void* const* d_in, const int* in_sizes, int n_in,
                              void* d_out, int out_size) {
    const float* input_data = (const float*)d_in[0];
    const float* h0         = (const float*)d_in[1];
    const float* c0         = (const float*)d_in[2];
    const int*   ped        = (const int*)  d_in[3];
    const float* W_emb      = (const float*)d_in[4];
    const float* b_emb      = (const float*)d_in[5];
    const float* W_ih       = (const float*)d_in[6];
    const float* W_hh       = (const float*)d_in[7];
    const float* b_ih       = (const float*)d_in[8];
    const float* b_hh       = (const float*)d_in[9];
    const float* W_out      = (const float*)d_in[10];
    const float* b_out      = (const float*)d_in[11];

    float* out   = (float*)d_out;
    float* out_y = out;                                      // [S][N][5]
    float* out_h = out + (size_t)S_LEN * N_SEQ * OUT_DIM;    // [N][128]
    float* out_c = out_h + (size_t)N_SEQ * RDIM;             // [N][128]

    prep_w<<<48, 128>>>(W_ih, W_hh);
    prep_bias<<<1, 512>>>(b_ih, b_hh);

    cudaFuncSetAttribute(lstm_mma, cudaFuncAttributeMaxDynamicSharedMemorySize, SMEM_TOTAL);
    lstm_mma<<<N_SEQ / TILE, NTHREADS, SMEM_TOTAL>>>(
        input_data, h0, c0, ped, W_emb, b_emb, W_out, b_out, out_y, out_h, out_c);
}

// round 9
// speedup vs baseline: 3.0807x; 1.0186x over previous
#include <cuda_runtime.h>
#include <cuda_fp16.h>
#include <cstdint>
#include <cstddef>

#define S_LEN   64
#define N_SEQ   65536
#define RDIM    128
#define OUT_DIM 5
#define TILE    64
#define NTHREADS 256
#define KDIM    192
#define NKC     12                      // k16 chunks per half
#define SLOTS_PER_STEP 24               // 2 halves x 12 kc
#define TOTAL_SLOTS (S_LEN * SLOTS_PER_STEP)   // 1536
#define SLOT_BYTES 8192                 // fp16: plane0 (k0-7) + plane1 (k8-15)
#define NBUF 4
#define APITCH 384                      // A row pitch bytes (192 k * 2B)

// ---- SMEM offsets (bytes), total 101456 -> 2 CTAs/SM ----
#define OFF_AHI   0          // 64*384 = 24576 (fp16 hi: e | h)
#define OFF_B     24576      // 4 x 8192 = 32768
#define OFF_C     57344      // 64*128 f32 = 32768
#define OFF_RED   90112      // 64*4*5 f32 = 5120
#define OFF_BIAS  95232      // 512 f32
#define OFF_WOUT  97280      // 640 f32
#define OFF_X     99840      // 128 f32
#define OFF_MASK  100352     // 64 i32
#define OFF_WEMB  100608     // 128 f32
#define OFF_BEMB  101120     // 64 f32
#define OFF_BOUT  101376     // 8 f32
#define OFF_MBAR  101408     // 4 x 8 mbarriers
#define SMEM_TOTAL 101440

// ---- device scratch ----
__device__ __align__(16) unsigned char g_Bstream[SLOTS_PER_STEP * SLOT_BYTES]; // 192KB
__device__ float g_bias[512];

// ---- helpers ----
__device__ __forceinline__ uint32_t pack2h(float a, float b) {
    __half2 v = __floats2half2_rn(a, b);
    return *reinterpret_cast<uint32_t*>(&v);
}
__device__ __forceinline__ float sigf(float x) { return __fdividef(1.f, 1.f + __expf(-x)); }
__device__ __forceinline__ float tanh_(float x) { return fmaf(2.f, sigf(2.f * x), -1.f); }

#define MBINIT(a, c) asm volatile("mbarrier.init.shared.b64 [%0], %1;" :: "r"(a), "r"(c) : "memory")
#define MB_EXPECT_TX(a, bytes) asm volatile( \
    "mbarrier.arrive.expect_tx.shared.b64 _, [%0], %1;" :: "r"(a), "r"(bytes) : "memory")
#define BULK_G2S(dst, src, bytes, mbar) asm volatile( \
    "cp.async.bulk.shared::cluster.global.mbarrier::complete_tx::bytes [%0], [%1], %2, [%3];" \
    :: "r"(dst), "l"(src), "r"(bytes), "r"(mbar) : "memory")
#define FENCE_PROXY() asm volatile("fence.proxy.async.shared::cta;" ::: "memory")

#define MBAR_WAIT(mbar, par) do { \
    uint32_t _m = (mbar); uint32_t _p = (par); uint32_t _d; \
    asm volatile("{\n\t.reg .pred p;\n\t" \
        "mbarrier.try_wait.parity.acquire.cta.shared::cta.b64 p, [%1], %2;\n\t" \
        "selp.b32 %0, 1, 0, p;\n\t}" : "=r"(_d) : "r"(_m), "r"(_p) : "memory"); \
    if (!_d) { \
        asm volatile("{\n\t.reg .pred P1;\n\t" \
            "WL_%=:\n\t" \
            "mbarrier.try_wait.parity.acquire.cta.shared::cta.b64 P1, [%0], %1, 0x989680;\n\t" \
            "@P1 bra.uni WD_%=;\n\t" \
            "bra.uni WL_%=;\n\t" \
            "WD_%=:\n\t}" :: "r"(_m), "r"(_p) : "memory"); \
    } \
} while (0)

__device__ __forceinline__ void ldsm4(uint32_t* r, uint32_t addr) {
    asm volatile("ldmatrix.sync.aligned.m8n8.x4.shared.b16 {%0,%1,%2,%3}, [%4];"
        : "=r"(r[0]), "=r"(r[1]), "=r"(r[2]), "=r"(r[3]) : "r"(addr));
}
__device__ __forceinline__ void mma16816h(float* c, const uint32_t* a, uint32_t b0, uint32_t b1) {
    asm volatile("mma.sync.aligned.m16n8k16.row.col.f32.f16.f16.f32 "
        "{%0,%1,%2,%3}, {%4,%5,%6,%7}, {%8,%9}, {%0,%1,%2,%3};"
        : "+f"(c[0]), "+f"(c[1]), "+f"(c[2]), "+f"(c[3])
        : "r"(a[0]), "r"(a[1]), "r"(a[2]), "r"(a[3]), "r"(b0), "r"(b1));
}

// A byte address with per-row XOR swizzle (conflict-free ldmatrix at pitch 384)
__device__ __forceinline__ uint32_t a_addr(uint32_t base, int m, int kb) {
    uint32_t kb16 = (uint32_t)kb & ~15u, off = (uint32_t)kb & 15u;
    return base + (uint32_t)m * APITCH + (kb16 ^ (((uint32_t)m & 7u) << 4)) + off;
}

// ---- prep: B stream, fp16. slot = nh*12+kc. Row j (0..255): r_local=j>>2, gate=j&3.
// Layout per slot: [0,4K) k0-7 | [4K,8K) k8-15
__global__ void prep_w(const float* __restrict__ Wih, const float* __restrict__ Whh) {
    int idx = blockIdx.x * 128 + threadIdx.x;      // 0..6143
    int slot = idx >> 8, j = idx & 255;
    int nh = slot / 12, kc = slot % 12;
    int gi = (j & 3) * 128 + nh * 64 + (j >> 2);
    uint32_t hi[8];
    #pragma unroll
    for (int p = 0; p < 8; ++p) {
        int k0 = kc * 16 + p * 2;
        float w0 = (k0     < 64) ? Wih[gi * 64 + k0]     : Whh[gi * 128 + k0 - 64];
        float w1 = (k0 + 1 < 64) ? Wih[gi * 64 + k0 + 1] : Whh[gi * 128 + k0 + 1 - 64];
        hi[p] = pack2h(w0, w1);
    }
    uint4* base = (uint4*)(g_Bstream + (size_t)slot * SLOT_BYTES + j * 16);
    base[0]         = make_uint4(hi[0], hi[1], hi[2], hi[3]);   // plane0
    base[4096 / 16] = make_uint4(hi[4], hi[5], hi[6], hi[7]);   // plane1
}
__global__ void prep_bias(const float* __restrict__ bih, const float* __restrict__ bhh) {
    int t = threadIdx.x; g_bias[t] = bih[t] + bhh[t];
}

// ---- main kernel: TILE=64, 256 threads, 2 CTAs/SM, bulk-copied B stream ----
__global__ void __launch_bounds__(NTHREADS, 2)
lstm_mma(const float* __restrict__ input_data,
         const float* __restrict__ h0,
         const float* __restrict__ c0,
         const int*   __restrict__ ped_mask,
         const float* __restrict__ W_emb,
         const float* __restrict__ b_emb,
         const float* __restrict__ W_out,
         const float* __restrict__ b_out,
         float* __restrict__ out_y,
         float* __restrict__ out_h,
         float* __restrict__ out_c)
{
    extern __shared__ unsigned char smem[];
    const uint32_t sbase = (uint32_t)__cvta_generic_to_shared(smem);
    const int t = threadIdx.x, lane = t & 31, wid = t >> 5;     // 8 warps
    const int warp_m = wid >> 2, warp_n = wid & 3;              // 2 x 4
    const int n0 = blockIdx.x * TILE;

    float* sC    = (float*)(smem + OFF_C);
    float* sRed  = (float*)(smem + OFF_RED);
    float* sBias = (float*)(smem + OFF_BIAS);
    float* sWout = (float*)(smem + OFF_WOUT);
    float* sX    = (float*)(smem + OFF_X);
    int*   sMask = (int*)  (smem + OFF_MASK);
    float* sWemb = (float*)(smem + OFF_WEMB);
    float* sBemb = (float*)(smem + OFF_BEMB);
    float* sBout = (float*)(smem + OFF_BOUT);

    // stage constants
    for (int i = t; i < 512; i += NTHREADS) sBias[i] = g_bias[i];
    for (int i = t; i < 640; i += NTHREADS) sWout[i] = W_out[i];
    if (t < 128) sWemb[t] = W_emb[t];
    else if (t < 192) sBemb[t - 128] = b_emb[t - 128];
    else if (t < 197) sBout[t - 192] = b_out[t - 192];

    // init mbarriers
    if (t == 0) {
        #pragma unroll
        for (int s = 0; s < NBUF; ++s) MBINIT(sbase + OFF_MBAR + s * 8, 1);
        FENCE_PROXY();
    }

    // init h -> A (fp16 hi), c -> sC
    {
        int m = t >> 2, rblk = (t & 3) * 32;
        const float4* hp = (const float4*)&h0[(size_t)(n0 + m) * RDIM + rblk];
        const float4* cp = (const float4*)&c0[(size_t)(n0 + m) * RDIM + rblk];
        #pragma unroll
        for (int jj = 0; jj < 8; ++jj) {
            float4 hv = hp[jj], cv = cp[jj];
            *(float4*)&sC[m * 128 + rblk + jj * 4] = cv;
            int r0 = rblk + jj * 4;
            uint32_t aH0 = a_addr(sbase + OFF_AHI, m, 128 + 2 * r0);
            uint32_t aH1 = a_addr(sbase + OFF_AHI, m, 128 + 2 * r0 + 4);
            asm volatile("st.shared.b32 [%0], %1;" :: "r"(aH0), "r"(pack2h(hv.x, hv.y)));
            asm volatile("st.shared.b32 [%0], %1;" :: "r"(aH1), "r"(pack2h(hv.z, hv.w)));
        }
    }
    __syncthreads();

    // prologue: slots 0,1,2 in flight via bulk copy
    if (t == 0) {
        #pragma unroll
        for (int s = 0; s < 3; ++s) {
            uint32_t mb = sbase + OFF_MBAR + (uint32_t)s * 8;
            MB_EXPECT_TX(mb, SLOT_BYTES);
            BULK_G2S(sbase + OFF_B + (uint32_t)s * SLOT_BYTES,
                     g_Bstream + (size_t)s * SLOT_BYTES, SLOT_BYTES, mb);
        }
    }

    float hpend[16];

    #pragma unroll 1
    for (int st = 0; st < S_LEN; ++st) {
        // stage x, mask
        if (t < 32) {
            ((float4*)sX)[t] = ((const float4*)(input_data + ((size_t)st * N_SEQ + n0) * 2))[t];
        } else if (t < 48) {
            ((int4*)sMask)[t - 32] = ((const int4*)(ped_mask + (size_t)st * N_SEQ + n0))[t - 32];
        }
        __syncthreads();

        // embedding -> A cols 0..63 (fp16 hi)
        {
            int kp = lane, sg = wid;          // 8 warps x 8 seqs = 64
            float w00 = sWemb[kp * 4], w01 = sWemb[kp * 4 + 1];
            float w10 = sWemb[kp * 4 + 2], w11 = sWemb[kp * 4 + 3];
            float bb0 = sBemb[kp * 2], bb1 = sBemb[kp * 2 + 1];
            #pragma unroll
            for (int q = 0; q < 8; ++q) {
                int s2 = sg * 8 + q;
                float x0 = sX[s2 * 2], x1 = sX[s2 * 2 + 1];
                float e0 = fmaxf(fmaf(w00, x0, fmaf(w01, x1, bb0)), 0.f);
                float e1 = fmaxf(fmaf(w10, x0, fmaf(w11, x1, bb1)), 0.f);
                uint32_t aH = a_addr(sbase + OFF_AHI, s2, kp * 4);
                asm volatile("st.shared.b32 [%0], %1;" :: "r"(aH), "r"(pack2h(e0, e1)));
            }
        }

        // ---- two halves: gates for r in [nh*64, nh*64+64) ----
        #pragma unroll 1
        for (int nh = 0; nh < 2; ++nh) {
            float acc[2][8][4];
            #pragma unroll
            for (int a = 0; a < 2; ++a)
                #pragma unroll
                for (int b = 0; b < 8; ++b)
                    #pragma unroll
                    for (int d = 0; d < 4; ++d) acc[a][b][d] = 0.f;

            #pragma unroll 1
            for (int kc = 0; kc < NKC; ++kc) {
                int g = st * SLOTS_PER_STEP + nh * NKC + kc;
                __syncthreads();       // all reads of buffer (g+3)%NBUF (slot g-1) done
                int q = g + 3;
                if (t == 0 && q < TOTAL_SLOTS) {
                    uint32_t mb = sbase + OFF_MBAR + (uint32_t)(q % NBUF) * 8;
                    MB_EXPECT_TX(mb, SLOT_BYTES);
                    BULK_G2S(sbase + OFF_B + (uint32_t)(q % NBUF) * SLOT_BYTES,
                             g_Bstream + (size_t)(q % SLOTS_PER_STEP) * SLOT_BYTES,
                             SLOT_BYTES, mb);
                }
                MBAR_WAIT(sbase + OFF_MBAR + (uint32_t)(g % NBUF) * 8, (uint32_t)((g >> 2) & 1));
                uint32_t sbuf = sbase + OFF_B + (uint32_t)(g % NBUF) * SLOT_BYTES;

                // A fragments (hi only) for 2 m-tiles
                uint32_t ah[2][4];
                int arow = warp_m * 32 + (lane & 15);
                int akb  = kc * 32 + ((lane >> 4) << 4);
                ldsm4(ah[0], a_addr(sbase + OFF_AHI, arow, akb));
                ldsm4(ah[1], a_addr(sbase + OFF_AHI, arow + 16, akb));
                // B: 4 groups of 2 n8-tiles
                int msel = lane >> 3, r8 = lane & 7;
                uint32_t brow_off = (uint32_t)(warp_n * 64 + ((msel >> 1) << 3) + r8) * 16u
                                  + (uint32_t)(msel & 1) * 4096u;
                #pragma unroll
                for (int p = 0; p < 4; ++p) {
                    uint32_t bh[4];
                    ldsm4(bh, sbuf + brow_off + (uint32_t)p * 256u);
                    #pragma unroll
                    for (int mt = 0; mt < 2; ++mt) {
                        mma16816h(acc[mt][2 * p],     ah[mt], bh[0], bh[1]);
                        mma16816h(acc[mt][2 * p + 1], ah[mt], bh[2], bh[3]);
                    }
                }
            }

            // ---- cell for this half ----
            const int odd = lane & 1;
            #pragma unroll
            for (int mt = 0; mt < 2; ++mt) {
                #pragma unroll
                for (int nt = 0; nt < 8; ++nt) {
                    float c0 = acc[mt][nt][0], c1 = acc[mt][nt][1];
                    float c2 = acc[mt][nt][2], c3 = acc[mt][nt][3];
                    float e0 = __shfl_xor_sync(0xffffffffu, c0, 1);
                    float e1 = __shfl_xor_sync(0xffffffffu, c1, 1);
                    float e2 = __shfl_xor_sync(0xffffffffu, c2, 1);
                    float e3 = __shfl_xor_sync(0xffffffffu, c3, 1);
                    int mrow = warp_m * 32 + mt * 16 + (lane >> 2) + (odd ? 8 : 0);
                    int rl   = warp_n * 16 + nt * 2 + ((lane & 3) >> 1);
                    int r    = nh * 64 + rl;
                    float zi = odd ? e2 : c0;
                    float zf = odd ? e3 : c1;
                    float zg = odd ? c2 : e0;
                    float zo = odd ? c3 : e1;
                    zi += sBias[r]; zf += sBias[128 + r];
                    zg += sBias[256 + r]; zo += sBias[384 + r];
                    float co = sC[mrow * 128 + r];
                    float cn = fmaf(sigf(zf), co, sigf(zi) * tanh_(zg));
                    float hn = sigf(zo) * tanh_(cn);
                    int msk = sMask[mrow];
                    if (msk) sC[mrow * 128 + r] = cn;
                    if (nh == 0) {
                        hpend[mt * 8 + nt] = hn;
                    } else if (msk) {
                        uint32_t aH = a_addr(sbase + OFF_AHI, mrow, 128 + 2 * r);
                        __half bh16 = __float2half_rn(hn);
                        asm volatile("st.shared.b16 [%0], %1;" :: "r"(aH), "h"(*(uint16_t*)&bh16));
                    }
                }
            }
        }

        // flush pending half-0 h writes (GEMMs done reading A)
        #pragma unroll
        for (int mt = 0; mt < 2; ++mt) {
            #pragma unroll
            for (int nt = 0; nt < 8; ++nt) {
                int mrow = warp_m * 32 + mt * 16 + (lane >> 2) + ((lane & 1) ? 8 : 0);
                int r    = warp_n * 16 + nt * 2 + ((lane & 3) >> 1);
                if (sMask[mrow]) {
                    uint32_t aH = a_addr(sbase + OFF_AHI, mrow, 128 + 2 * r);
                    __half bh16 = __float2half_rn(hpend[mt * 8 + nt]);
                    asm volatile("st.shared.b16 [%0], %1;" :: "r"(aH), "h"(*(uint16_t*)&bh16));
                }
            }
        }
        __syncthreads();

        // ---- output head (h from fp16-hi plane) ----
        {
            int s = t & 63, part = t >> 6;    // 4 parts x 32 r
            float o0 = 0, o1 = 0, o2 = 0, o3 = 0, o4 = 0;
            #pragma unroll
            for (int rr = 0; rr < 16; ++rr) {
                int r0 = part * 32 + rr * 2;
                uint32_t aH = a_addr(sbase + OFF_AHI, s, 128 + 2 * r0);
                uint32_t vh;
                asm volatile("ld.shared.b32 %0, [%1];" : "=r"(vh) : "r"(aH));
                __half2 h2 = *reinterpret_cast<__half2*>(&vh);
                float ha = __half2float(h2.x);
                float hb = __half2float(h2.y);
                o0 = fmaf(ha, sWout[r0], fmaf(hb, sWout[r0 + 1], o0));
                o1 = fmaf(ha, sWout[128 + r0], fmaf(hb, sWout[128 + r0 + 1], o1));
                o2 = fmaf(ha, sWout[256 + r0], fmaf(hb, sWout[256 + r0 + 1], o2));
                o3 = fmaf(ha, sWout[384 + r0], fmaf(hb, sWout[384 + r0 + 1], o3));
                o4 = fmaf(ha, sWout[512 + r0], fmaf(hb, sWout[512 + r0 + 1], o4));
            }
            float* rp = &sRed[(s * 4 + part) * 5];
            rp[0] = o0; rp[1] = o1; rp[2] = o2; rp[3] = o3; rp[4] = o4;
        }
        __syncthreads();
        for (int idx = t; idx < 320; idx += NTHREADS) {
            int s2 = idx / 5, oo = idx % 5;
            float v = 0.f;
            if (sMask[s2]) {
                v = sRed[(s2 * 4 + 0) * 5 + oo] + sRed[(s2 * 4 + 1) * 5 + oo]
                  + sRed[(s2 * 4 + 2) * 5 + oo] + sRed[(s2 * 4 + 3) * 5 + oo] + sBout[oo];
            }
            out_y[((size_t)st * N_SEQ + n0 + s2) * OUT_DIM + oo] = v;
        }
        __syncthreads();
    }

    // ---- final h, c writeback ----
    {
        int m = t >> 2, rblk = (t & 3) * 32;
        float4* hp = (float4*)&out_h[(size_t)(n0 + m) * RDIM + rblk];
        float4* cp = (float4*)&out_c[(size_t)(n0 + m) * RDIM + rblk];
        #pragma unroll
        for (int jj = 0; jj < 8; ++jj) {
            int r0 = rblk + jj * 4;
            uint32_t vh0, vh1;
            uint32_t aH0 = a_addr(sbase + OFF_AHI, m, 128 + 2 * r0);
            uint32_t aH1 = a_addr(sbase + OFF_AHI, m, 128 + 2 * r0 + 4);
            asm volatile("ld.shared.b32 %0, [%1];" : "=r"(vh0) : "r"(aH0));
            asm volatile("ld.shared.b32 %0, [%1];" : "=r"(vh1) : "r"(aH1));
            __half2 h2a = *reinterpret_cast<__half2*>(&vh0);
            __half2 h2b = *reinterpret_cast<__half2*>(&vh1);
            float4 hv;
            hv.x = __half2float(h2a.x);
            hv.y = __half2float(h2a.y);
            hv.z = __half2float(h2b.x);
            hv.w = __half2float(h2b.y);
            hp[jj] = hv;
            cp[jj] = *(float4*)&sC[m * 128 + r0];
        }
    }
}

extern "C" void kernel_launch(void* const* d_in, const int* in_sizes, int n_in,
                              void* d_out, int out_size) {
    const float* input_data = (const float*)d_in[0];
    const float* h0         = (const float*)d_in[1];
    const float* c0         = (const float*)d_in[2];
    const int*   ped        = (const int*)  d_in[3];
    const float* W_emb      = (const float*)d_in[4];
    const float* b_emb      = (const float*)d_in[5];
    const float* W_ih       = (const float*)d_in[6];
    const float* W_hh       = (const float*)d_in[7];
    const float* b_ih       = (const float*)d_in[8];
    const float* b_hh       = (const float*)d_in[9];
    const float* W_out      = (const float*)d_in[10];
    const float* b_out      = (const float*)d_in[11];

    float* out   = (float*)d_out;
    float* out_y = out;                                      // [S][N][5]
    float* out_h = out + (size_t)S_LEN * N_SEQ * OUT_DIM;    // [N][128]
    float* out_c = out_h + (size_t)N_SEQ * RDIM;             // [N][128]

    prep_w<<<48, 128>>>(W_ih, W_hh);
    prep_bias<<<1, 512>>>(b_ih, b_hh);

    cudaFuncSetAttribute(lstm_mma, cudaFuncAttributeMaxDynamicSharedMemorySize, SMEM_TOTAL);
    lstm_mma<<<N_SEQ / TILE, NTHREADS, SMEM_TOTAL>>>(
        input_data, h0, c0, ped, W_emb, b_emb, W_out, b_out, out_y, out_h, out_c);
}